// round 6
// baseline (speedup 1.0000x reference)
#include <cuda_runtime.h>
#include <math.h>

#define HD 128
#define NB 16     // batches
#define NV 4      // vocab
#define NL 6      // layers
#define MAXN 20000
#define MAXE 600000
#define TPB 128   // threads per MMA CTA (4 warps, 2x2 grid of 64x64 tiles)

// ---------------- scratch (static device allocs; cudaMalloc is banned) -----
__device__ float g_hV[MAXN * HD];
__device__ float g_agg[MAXN * HD];
__device__ float g_tmp[MAXN * HD];
__device__ float g_ffn[MAXN * 4 * HD];
__device__ float g_xvs[MAXN * HD];
__device__ float g_xvd[MAXN * HD];
__device__ float g_deg[MAXN];
__device__ float g_pool[NB * HD];
__device__ float g_pcnt[NB];

// ---------------- tiny utility kernels -------------------------------------
__global__ void zero_kernel(float* __restrict__ p, int n) {
    int i = blockIdx.x * blockDim.x + threadIdx.x;
    if (i < n) p[i] = 0.f;
}

__global__ void copy_kernel(float* __restrict__ dst, const float* __restrict__ src, int n) {
    int i = blockIdx.x * blockDim.x + threadIdx.x;
    if (i < n) dst[i] = src[i];
}

__global__ void deg_kernel(const int* __restrict__ src, float* __restrict__ deg, int E) {
    int i = blockIdx.x * blockDim.x + threadIdx.x;
    if (i < E) atomicAdd(&deg[src[i]], 1.f);
}

// ---------------- tf32 + fragment-major helpers ------------------------------
__device__ __forceinline__ unsigned f2tf(float f) {
    unsigned r;
    asm("cvt.rna.tf32.f32 %0, %1;" : "=r"(r) : "f"(f));
    return r;
}

__device__ __forceinline__ void mma_tf32(float c[4],
                                         unsigned a0, unsigned a1, unsigned a2, unsigned a3,
                                         unsigned b0, unsigned b1) {
    asm volatile(
        "mma.sync.aligned.m16n8k8.row.col.f32.tf32.tf32.f32 "
        "{%0,%1,%2,%3}, {%4,%5,%6,%7}, {%8,%9}, {%0,%1,%2,%3};"
        : "+f"(c[0]), "+f"(c[1]), "+f"(c[2]), "+f"(c[3])
        : "r"(a0), "r"(a1), "r"(a2), "r"(a3), "r"(b0), "r"(b1));
}

// ---- split LDG / STS for A chunks (128 rows x 32 k) -> 32 groups, stride 132
__device__ __forceinline__ void ldg_A(float4 v[8], const float* __restrict__ A,
                                      size_t lda, int row0, int M, int kglob0, int tid)
{
#pragma unroll
    for (int it = 0; it < 8; ++it) {
        int item = tid + it * TPB;
        int row = item >> 3, q = item & 7;
        v[it] = make_float4(0.f, 0.f, 0.f, 0.f);
        if (row0 + row < M)
            v[it] = *(const float4*)(A + (size_t)(row0 + row) * lda + kglob0 + q * 4);
    }
}

__device__ __forceinline__ void sts_A(unsigned* __restrict__ As, const float4 v[8], int tid)
{
#pragma unroll
    for (int it = 0; it < 8; ++it) {
        int item = tid + it * TPB;
        int row = item >> 3, q = item & 7;
        int g = ((row >> 4) << 2) + (q >> 1);
        int base = g * 132 + ((row & 7) << 4) + ((row >> 3) & 1) + ((q & 1) << 1);
        As[base + 0]  = f2tf(v[it].x);
        As[base + 4]  = f2tf(v[it].y);
        As[base + 8]  = f2tf(v[it].z);
        As[base + 12] = f2tf(v[it].w);
    }
}

// ---- split LDG / STS for B chunks (32 k x 128 n) -> 64 groups, stride 66
__device__ __forceinline__ void ldg_B(float4 v[8], const float* __restrict__ B,
                                      size_t ldb, int kglob0, int n0, int tid)
{
#pragma unroll
    for (int it = 0; it < 8; ++it) {
        int item = tid + it * TPB;
        int k = item >> 5, q = item & 31;
        v[it] = *(const float4*)(B + (size_t)(kglob0 + k) * ldb + n0 + q * 4);
    }
}

__device__ __forceinline__ void sts_B(unsigned* __restrict__ Bs, const float4 v[8], int tid)
{
#pragma unroll
    for (int it = 0; it < 8; ++it) {
        int item = tid + it * TPB;
        int k = item >> 5, q = item & 31;
        int gb = ((k >> 3) << 4) + (q >> 1);
        int base = gb * 66 + ((q & 1) << 5) + ((k & 3) << 1) + ((k >> 2) & 1);
        Bs[base + 0]  = f2tf(v[it].x);
        Bs[base + 8]  = f2tf(v[it].y);
        Bs[base + 16] = f2tf(v[it].z);
        Bs[base + 24] = f2tf(v[it].w);
    }
}

// one 32-k chunk of warp-tile 64x64 mma (4 mtiles x 8 ntiles)
__device__ __forceinline__ void mma_chunk(float acc[4][8][4],
                                          const unsigned* __restrict__ Af, int mg0, int gs, int gk0,
                                          const unsigned* __restrict__ Bs, int ng0, int lane)
{
#pragma unroll
    for (int kt = 0; kt < 4; ++kt) {
        uint4 a[4]; uint2 b[8];
#pragma unroll
        for (int mi = 0; mi < 4; ++mi)
            a[mi] = *(const uint4*)&Af[((mg0 + mi) * gs + gk0 + kt) * 132 + lane * 4];
#pragma unroll
        for (int ni = 0; ni < 8; ++ni)
            b[ni] = *(const uint2*)&Bs[((kt << 4) + ng0 + ni) * 66 + lane * 2];
#pragma unroll
        for (int mi = 0; mi < 4; ++mi)
#pragma unroll
            for (int ni = 0; ni < 8; ++ni)
                mma_tf32(acc[mi][ni], a[mi].x, a[mi].y, a[mi].z, a[mi].w,
                         b[ni].x, b[ni].y);
    }
}

#define ACC_ZERO(acc) \
    _Pragma("unroll") for (int mi = 0; mi < 4; ++mi) \
    _Pragma("unroll") for (int ni = 0; ni < 8; ++ni) \
    _Pragma("unroll") for (int j = 0; j < 4; ++j) acc[mi][ni][j] = 0.f;

// ---------------- fused edge MLP (tf32, 64x64 warp tiles, double-buffered) --
// smem: WB = W1a resident (4 chunks x 4224), aliased as Cs after stage 1.
//       Asb[2] = ping-pong streamed chunk (hE, then W2/W3).
#define WB_WORDS (4 * 64 * 66)     // 16896 (= 128 groups * 132 for Cs)
#define CHUNK_WORDS (32 * 132)     // 4224
#define EDGE_SMEM ((WB_WORDS + 2 * CHUNK_WORDS + 256) * 4)
#define GEMM_SMEM ((4 * CHUNK_WORDS) * 4)

__global__ __launch_bounds__(TPB, 2)
void edge_mlp_tc(const float* __restrict__ hE,
                 const int* __restrict__ esrc,
                 const int* __restrict__ edst,
                 const float* __restrict__ XVs,
                 const float* __restrict__ XVd,
                 const float* __restrict__ W1a, const float* __restrict__ b1,
                 const float* __restrict__ W2,  const float* __restrict__ b2,
                 const float* __restrict__ W3,  const float* __restrict__ b3,
                 float* __restrict__ agg, int E)
{
    extern __shared__ unsigned smem_u[];
    unsigned* WB = smem_u;                  // W1a resident; later Cs
    unsigned* Asb[2] = { WB + WB_WORDS, WB + WB_WORDS + CHUNK_WORDS };
    int* s_src = (int*)(WB + WB_WORDS + 2 * CHUNK_WORDS);
    int* s_dst = s_src + 128;

    const int tid = threadIdx.x;
    const int lane = tid & 31;
    const int wid = tid >> 5;
    const int mrow0 = (wid >> 1) * 64;
    const int ncol0 = (wid & 1) * 64;
    const int mg0 = mrow0 >> 4;   // 0 or 4
    const int ng0 = ncol0 >> 3;   // 0 or 8
    const int lq = lane >> 2;
    const int lr = lane & 3;
    const int e0 = blockIdx.x * 128;

    if (tid < 128) {
        int e = e0 + tid;
        s_src[tid] = (e < E) ? esrc[e] : -1;
        s_dst[tid] = (e < E) ? edst[e] : -1;
    }

    float4 v[8];
    float acc[4][8][4];

    // ================= stage 1: hE @ W1a (W resident, A double-buffered) ====
    ACC_ZERO(acc);
#pragma unroll
    for (int c = 0; c < 4; ++c) {
        ldg_B(v, W1a, HD, c * 32, 0, tid);
        sts_B(WB + c * CHUNK_WORDS, v, tid);
    }
    ldg_A(v, hE, HD, e0, E, 0, tid);
    sts_A(Asb[0], v, tid);
    __syncthreads();

#pragma unroll
    for (int kc = 0; kc < 4; ++kc) {
        if (kc < 3) ldg_A(v, hE, HD, e0, E, (kc + 1) * 32, tid);
        mma_chunk(acc, Asb[kc & 1], mg0, 4, 0, WB + kc * CHUNK_WORDS, ng0, lane);
        if (kc < 3) sts_A(Asb[(kc + 1) & 1], v, tid);
        __syncthreads();
    }

    unsigned* Cs = WB;   // alias — all W1a reads are done

    // prefetch W2 chunk 0 (lands while epilogue runs)
    ldg_B(v, W2, HD, 0, 0, tid);

    // epilogue 1: + b1 + XVs[src] + XVd[dst], relu, tf32 -> Cs fragment-major
#pragma unroll
    for (int ni = 0; ni < 8; ++ni) {
        int cb = ncol0 + ni * 8 + 2 * lr;
        float b10 = b1[cb], b11 = b1[cb + 1];
#pragma unroll
        for (int mi = 0; mi < 4; ++mi) {
#pragma unroll
            for (int h = 0; h < 2; ++h) {
                int r = mrow0 + mi * 16 + lq + h * 8;
                int ns = s_src[r], nd = s_dst[r];
                float v0 = 0.f, v1 = 0.f;
                if (ns >= 0) {
                    float2 xs = *(const float2*)(XVs + (size_t)ns * HD + cb);
                    float2 xd = *(const float2*)(XVd + (size_t)nd * HD + cb);
                    v0 = acc[mi][ni][h * 2 + 0] + b10 + xs.x + xd.x;
                    v1 = acc[mi][ni][h * 2 + 1] + b11 + xs.y + xd.y;
                }
#pragma unroll
                for (int e = 0; e < 2; ++e) {
                    int t = 2 * lr + e;
                    Cs[((mg0 + mi) * 16 + ng0 + ni) * 132
                       + ((lq * 4 + (t & 3)) << 2) + h + ((t >> 2) << 1)]
                        = f2tf(fmaxf(e ? v1 : v0, 0.f));
                }
            }
        }
    }
    sts_B(Asb[0], v, tid);
    __syncthreads();

    // ================= stage 2: C1 @ W2 (W double-buffered) =================
    ACC_ZERO(acc);
#pragma unroll
    for (int kc = 0; kc < 4; ++kc) {
        if (kc < 3) ldg_B(v, W2, HD, (kc + 1) * 32, 0, tid);
        mma_chunk(acc, Cs, mg0, 16, kc * 4, Asb[kc & 1], ng0, lane);
        if (kc < 3) sts_B(Asb[(kc + 1) & 1], v, tid);
        __syncthreads();
    }

    // prefetch W3 chunk 0
    ldg_B(v, W3, HD, 0, 0, tid);

    // epilogue 2: + b2, relu, tf32 -> Cs (in place, own slots)
#pragma unroll
    for (int ni = 0; ni < 8; ++ni) {
        int cb = ncol0 + ni * 8 + 2 * lr;
        float b20 = b2[cb], b21 = b2[cb + 1];
#pragma unroll
        for (int mi = 0; mi < 4; ++mi) {
#pragma unroll
            for (int h = 0; h < 2; ++h) {
#pragma unroll
                for (int e = 0; e < 2; ++e) {
                    int t = 2 * lr + e;
                    float vv = acc[mi][ni][h * 2 + e] + (e ? b21 : b20);
                    Cs[((mg0 + mi) * 16 + ng0 + ni) * 132
                       + ((lq * 4 + (t & 3)) << 2) + h + ((t >> 2) << 1)]
                        = f2tf(fmaxf(vv, 0.f));
                }
            }
        }
    }
    sts_B(Asb[0], v, tid);
    __syncthreads();

    // ================= stage 3: C2 @ W3 =================
    ACC_ZERO(acc);
#pragma unroll
    for (int kc = 0; kc < 4; ++kc) {
        if (kc < 3) ldg_B(v, W3, HD, (kc + 1) * 32, 0, tid);
        mma_chunk(acc, Cs, mg0, 16, kc * 4, Asb[kc & 1], ng0, lane);
        if (kc < 3) sts_B(Asb[(kc + 1) & 1], v, tid);
        __syncthreads();
    }

    // epilogue 3: + b3, stage f32 row-major (pitch 132) into Cs for scatter
    float* CsF = (float*)Cs;
#pragma unroll
    for (int ni = 0; ni < 8; ++ni) {
        int cb = ncol0 + ni * 8 + 2 * lr;
        float b30 = b3[cb], b31 = b3[cb + 1];
#pragma unroll
        for (int mi = 0; mi < 4; ++mi) {
#pragma unroll
            for (int h = 0; h < 2; ++h) {
                int r = mrow0 + mi * 16 + lq + h * 8;
                CsF[r * 132 + cb]     = acc[mi][ni][h * 2 + 0] + b30;
                CsF[r * 132 + cb + 1] = acc[mi][ni][h * 2 + 1] + b31;
            }
        }
    }
    __syncthreads();

    // cooperative vector scatter: 128 rows x 32 float4
    for (int item = tid; item < 128 * 32; item += TPB) {
        int row = item >> 5, q = item & 31;
        int node = s_src[row];
        if (node >= 0) {
            const float4 vv = *(const float4*)(CsF + row * 132 + q * 4);
            float* p = agg + (size_t)node * HD + q * 4;
            asm volatile("red.global.add.v4.f32 [%0], {%1,%2,%3,%4};"
                         :: "l"(p), "f"(vv.x), "f"(vv.y), "f"(vv.z), "f"(vv.w)
                         : "memory");
        }
    }
}

// ---------------- tf32 node GEMM (128x128 tile, 64x64 warp tiles, dbuf) ----
// epi 0: relu(A@B + bias); epi 1: A@B + bias + res; epi 2: A@B
// blockIdx.z selects (B,C) or (B2,C2) for the fused pre-GEMM pair
__global__ __launch_bounds__(TPB, 2)
void gemm_tc(const float* __restrict__ A, const float* __restrict__ B,
             const float* __restrict__ B2,
             const float* __restrict__ bias, const float* __restrict__ res,
             float* __restrict__ C, float* __restrict__ C2,
             int M, int N, int K, int epi)
{
    extern __shared__ unsigned smem_u[];
    unsigned* Asb[2] = { smem_u, smem_u + CHUNK_WORDS };
    unsigned* Bsb[2] = { smem_u + 2 * CHUNK_WORDS, smem_u + 3 * CHUNK_WORDS };

    const int tid = threadIdx.x;
    const int lane = tid & 31;
    const int wid = tid >> 5;
    const int mrow0 = (wid >> 1) * 64;
    const int ncol0 = (wid & 1) * 64;
    const int mg0 = mrow0 >> 4;
    const int ng0 = ncol0 >> 3;
    const int lq = lane >> 2;
    const int lr = lane & 3;
    const int m0 = blockIdx.y * 128, n0 = blockIdx.x * 128;
    if (blockIdx.z) { B = B2; C = C2; }

    float4 va[8], vb[8];
    float acc[4][8][4];
    ACC_ZERO(acc);

    const int nkc = K / 32;
    ldg_A(va, A, K, m0, M, 0, tid);
    ldg_B(vb, B, N, 0, n0, tid);
    sts_A(Asb[0], va, tid);
    sts_B(Bsb[0], vb, tid);
    __syncthreads();

    for (int kc = 0; kc < nkc; ++kc) {
        if (kc + 1 < nkc) {
            ldg_A(va, A, K, m0, M, (kc + 1) * 32, tid);
            ldg_B(vb, B, N, (kc + 1) * 32, n0, tid);
        }
        mma_chunk(acc, Asb[kc & 1], mg0, 4, 0, Bsb[kc & 1], ng0, lane);
        if (kc + 1 < nkc) {
            sts_A(Asb[(kc + 1) & 1], va, tid);
            sts_B(Bsb[(kc + 1) & 1], vb, tid);
        }
        __syncthreads();
    }

#pragma unroll
    for (int ni = 0; ni < 8; ++ni) {
        int c = n0 + ncol0 + ni * 8 + 2 * lr;
        float bb0 = (epi == 2) ? 0.f : bias[c];
        float bb1 = (epi == 2) ? 0.f : bias[c + 1];
#pragma unroll
        for (int mi = 0; mi < 4; ++mi) {
#pragma unroll
            for (int h = 0; h < 2; ++h) {
                int r = m0 + mrow0 + mi * 16 + lq + h * 8;
                if (r < M) {
                    float v0 = acc[mi][ni][h * 2 + 0] + bb0;
                    float v1 = acc[mi][ni][h * 2 + 1] + bb1;
                    if (epi == 0) { v0 = fmaxf(v0, 0.f); v1 = fmaxf(v1, 0.f); }
                    else if (epi == 1) {
                        v0 += res[(size_t)r * N + c];
                        v1 += res[(size_t)r * N + c + 1];
                    }
                    C[(size_t)r * N + c]     = v0;
                    C[(size_t)r * N + c + 1] = v1;
                }
            }
        }
    }
}

// ---------------- layernorm kernels (one warp per node, H=128) -------------
__device__ __forceinline__ float warp_sum(float v) {
#pragma unroll
    for (int o = 16; o > 0; o >>= 1) v += __shfl_xor_sync(0xffffffffu, v, o);
    return v;
}

__global__ void agg_ln_kernel(float* __restrict__ hV, const float* __restrict__ agg,
                              const float* __restrict__ deg,
                              const float* __restrict__ g, const float* __restrict__ b,
                              int N)
{
    int warp = (blockIdx.x * blockDim.x + threadIdx.x) >> 5;
    int lane = threadIdx.x & 31;
    if (warp >= N) return;
    float d = fmaxf(deg[warp], 1.f);
    float x[4];
#pragma unroll
    for (int j = 0; j < 4; j++) {
        int c = j * 32 + lane;
        x[j] = hV[(size_t)warp * HD + c] + agg[(size_t)warp * HD + c] / d;
    }
    float s = warp_sum(x[0] + x[1] + x[2] + x[3]);
    float mu = s * (1.f / HD);
    float ss = warp_sum(x[0]*x[0] + x[1]*x[1] + x[2]*x[2] + x[3]*x[3]);
    float var = ss * (1.f / HD) - mu * mu;
    float inv = rsqrtf(var + 1e-5f);
#pragma unroll
    for (int j = 0; j < 4; j++) {
        int c = j * 32 + lane;
        hV[(size_t)warp * HD + c] = (x[j] - mu) * inv * g[c] + b[c];
    }
}

__global__ void ln_kernel(const float* __restrict__ x, float* __restrict__ out,
                          const float* __restrict__ g, const float* __restrict__ b,
                          int N)
{
    int warp = (blockIdx.x * blockDim.x + threadIdx.x) >> 5;
    int lane = threadIdx.x & 31;
    if (warp >= N) return;
    float v[4];
#pragma unroll
    for (int j = 0; j < 4; j++) v[j] = x[(size_t)warp * HD + j * 32 + lane];
    float s = warp_sum(v[0] + v[1] + v[2] + v[3]);
    float mu = s * (1.f / HD);
    float ss = warp_sum(v[0]*v[0] + v[1]*v[1] + v[2]*v[2] + v[3]*v[3]);
    float var = ss * (1.f / HD) - mu * mu;
    float inv = rsqrtf(var + 1e-5f);
#pragma unroll
    for (int j = 0; j < 4; j++) {
        int c = j * 32 + lane;
        out[(size_t)warp * HD + c] = (v[j] - mu) * inv * g[c] + b[c];
    }
}

// ---------------- pooling / heads ------------------------------------------
__global__ void pool_kernel(const float* __restrict__ hV, const int* __restrict__ batch_id,
                            float* __restrict__ pool, float* __restrict__ pcnt, int N)
{
    int i = blockIdx.x * blockDim.x + threadIdx.x;
    if (i < N * HD) {
        int n = i >> 7, c = i & 127;
        atomicAdd(&pool[batch_id[n] * HD + c], hV[i]);
    }
    if (i < N) atomicAdd(&pcnt[batch_id[i]], 1.f);
}

__global__ void head_kernel(const float* __restrict__ pool, const float* __restrict__ pcnt,
                            const float* __restrict__ P1, const float* __restrict__ P2,
                            const float* __restrict__ p2b, float* __restrict__ out)
{
    __shared__ float embs[NB * HD];
    __shared__ float t1[NB * HD];
    int tid = threadIdx.x;
    for (int i = tid; i < NB * HD; i += blockDim.x) {
        int bb = i >> 7;
        embs[i] = pool[i] / fmaxf(pcnt[bb], 1.f);
    }
    __syncthreads();
    for (int i = tid; i < NB * HD; i += blockDim.x) {
        int bb = i >> 7, j = i & 127;
        float s = 0.f;
        for (int k = 0; k < HD; k++) s += embs[bb * HD + k] * P1[k * HD + j];
        t1[i] = fmaxf(s, 0.f);
    }
    __syncthreads();
    for (int i = tid; i < NB * HD; i += blockDim.x) {
        int bb = i >> 7, j = i & 127;
        float s = p2b[j];
        for (int k = 0; k < HD; k++) s += t1[bb * HD + k] * P2[k * HD + j];
        out[i] = s;
    }
}

__global__ void logits_kernel(const float* __restrict__ hV, const int* __restrict__ S,
                              const float* __restrict__ R, const float* __restrict__ rb,
                              float* __restrict__ out, int N)
{
    __shared__ float Rs[HD * NV];
    __shared__ float rbs[NV];
    int tid = threadIdx.x;
    for (int i = tid; i < HD * NV; i += blockDim.x) Rs[i] = R[i];
    if (tid < NV) rbs[tid] = rb[tid];
    __syncthreads();
    int n = blockIdx.x * blockDim.x + tid;
    if (n < N) {
        float a0 = rbs[0], a1 = rbs[1], a2 = rbs[2], a3 = rbs[3];
        const float* h = hV + (size_t)n * HD;
#pragma unroll 8
        for (int k = 0; k < HD; k++) {
            float hv = h[k];
            a0 += hv * Rs[k * NV + 0];
            a1 += hv * Rs[k * NV + 1];
            a2 += hv * Rs[k * NV + 2];
            a3 += hv * Rs[k * NV + 3];
        }
        out[(size_t)n * NV + 0] = a0;
        out[(size_t)n * NV + 1] = a1;
        out[(size_t)n * NV + 2] = a2;
        out[(size_t)n * NV + 3] = a3;
        out[(size_t)N * NV + n] = (float)S[n];
    }
}

// ---------------- launch ----------------------------------------------------
extern "C" void kernel_launch(void* const* d_in, const int* in_sizes, int n_in,
                              void* d_out, int out_size)
{
    const float* h_V  = (const float*)d_in[0];
    const float* h_E  = (const float*)d_in[1];
    const int*   Eidx = (const int*)d_in[2];
    const int*   bid  = (const int*)d_in[3];
    const int*   S    = (const int*)d_in[4];
    const float* W1   = (const float*)d_in[5];
    const float* b1   = (const float*)d_in[6];
    const float* W2   = (const float*)d_in[7];
    const float* b2   = (const float*)d_in[8];
    const float* W3   = (const float*)d_in[9];
    const float* b3   = (const float*)d_in[10];
    const float* ln1g = (const float*)d_in[11];
    const float* ln1b = (const float*)d_in[12];
    const float* Wi   = (const float*)d_in[13];
    const float* bi   = (const float*)d_in[14];
    const float* Wo   = (const float*)d_in[15];
    const float* bo   = (const float*)d_in[16];
    const float* ln2g = (const float*)d_in[17];
    const float* ln2b = (const float*)d_in[18];
    const float* P1   = (const float*)d_in[19];
    const float* P2   = (const float*)d_in[20];
    const float* p2b  = (const float*)d_in[21];
    const float* R    = (const float*)d_in[22];
    const float* rb   = (const float*)d_in[23];

    const int N = in_sizes[0] / HD;
    const int E = in_sizes[2] / 2;
    const int* esrc = Eidx;
    const int* edst = Eidx + E;

    float *p_hV, *p_agg, *p_tmp, *p_ffn, *p_xvs, *p_xvd, *p_deg, *p_pool, *p_pcnt;
    cudaGetSymbolAddress((void**)&p_hV,   g_hV);
    cudaGetSymbolAddress((void**)&p_agg,  g_agg);
    cudaGetSymbolAddress((void**)&p_tmp,  g_tmp);
    cudaGetSymbolAddress((void**)&p_ffn,  g_ffn);
    cudaGetSymbolAddress((void**)&p_xvs,  g_xvs);
    cudaGetSymbolAddress((void**)&p_xvd,  g_xvd);
    cudaGetSymbolAddress((void**)&p_deg,  g_deg);
    cudaGetSymbolAddress((void**)&p_pool, g_pool);
    cudaGetSymbolAddress((void**)&p_pcnt, g_pcnt);

    cudaFuncSetAttribute(edge_mlp_tc,
                         cudaFuncAttributeMaxDynamicSharedMemorySize, EDGE_SMEM);
    cudaFuncSetAttribute(gemm_tc,
                         cudaFuncAttributeMaxDynamicSharedMemorySize, GEMM_SMEM);

    copy_kernel<<<(N * HD + 255) / 256, 256>>>(p_hV, h_V, N * HD);

    zero_kernel<<<(N + 255) / 256, 256>>>(p_deg, N);
    deg_kernel<<<(E + 255) / 256, 256>>>(esrc, p_deg, E);

    const int edge_grid = (E + 127) / 128;
    const int mtiles = (N + 127) / 128;

    for (int l = 0; l < NL; ++l) {
        const float* W1l = W1 + (size_t)l * 3 * HD * HD;
        // fused pre-GEMMs: XVs = hV @ W1[128:256], XVd = hV @ W1[256:384]
        gemm_tc<<<dim3(1, mtiles, 2), TPB, GEMM_SMEM>>>(
            p_hV, W1l + (size_t)HD * HD, W1l + (size_t)2 * HD * HD,
            nullptr, nullptr, p_xvs, p_xvd, N, HD, HD, 2);

        zero_kernel<<<(N * HD + 255) / 256, 256>>>(p_agg, N * HD);
        edge_mlp_tc<<<edge_grid, TPB, EDGE_SMEM>>>(
            h_E, esrc, edst, p_xvs, p_xvd,
            W1l, b1 + (size_t)l * HD,
            W2 + (size_t)l * HD * HD, b2 + (size_t)l * HD,
            W3 + (size_t)l * HD * HD, b3 + (size_t)l * HD,
            p_agg, E);
        agg_ln_kernel<<<(N + 7) / 8, 256>>>(p_hV, p_agg, p_deg,
                                            ln1g + (size_t)l * HD, ln1b + (size_t)l * HD, N);
        gemm_tc<<<dim3(4, mtiles, 1), TPB, GEMM_SMEM>>>(
            p_hV, Wi + (size_t)l * HD * 4 * HD, nullptr,
            bi + (size_t)l * 4 * HD, nullptr, p_ffn, nullptr, N, 4 * HD, HD, 0);
        gemm_tc<<<dim3(1, mtiles, 1), TPB, GEMM_SMEM>>>(
            p_ffn, Wo + (size_t)l * 4 * HD * HD, nullptr,
            bo + (size_t)l * HD, p_hV, p_tmp, nullptr, N, HD, 4 * HD, 1);
        ln_kernel<<<(N + 7) / 8, 256>>>(p_tmp, p_hV,
                                        ln2g + (size_t)l * HD, ln2b + (size_t)l * HD, N);
    }

    zero_kernel<<<(NB * HD + 255) / 256, 256>>>(p_pool, NB * HD);
    zero_kernel<<<1, 32>>>(p_pcnt, NB);
    pool_kernel<<<(N * HD + 255) / 256, 256>>>(p_hV, bid, p_pool, p_pcnt, N);

    float* out = (float*)d_out;
    head_kernel<<<1, 256>>>(p_pool, p_pcnt, P1, P2, p2b,
                            out + (size_t)N * NV + N);
    logits_kernel<<<(N + 255) / 256, 256>>>(p_hV, S, R, rb, out, N);
}

// round 7
// speedup vs baseline: 1.2188x; 1.2188x over previous
#include <cuda_runtime.h>
#include <math.h>

#define HD 128
#define NB 16     // batches
#define NV 4      // vocab
#define NL 6      // layers
#define MAXN 20000
#define MAXE 600000

// ---------------- scratch (static device allocs; cudaMalloc is banned) -----
__device__ float g_hV[MAXN * HD];
__device__ float g_agg[MAXN * HD];
__device__ float g_tmp[MAXN * HD];
__device__ float g_ffn[MAXN * 4 * HD];
__device__ float g_xvs[MAXN * HD];
__device__ float g_xvd[MAXN * HD];
__device__ float g_deg[MAXN];
__device__ float g_pool[NB * HD];
__device__ float g_pcnt[NB];

// ---------------- tiny utility kernels -------------------------------------
__global__ void zero_kernel(float* __restrict__ p, int n) {
    int i = blockIdx.x * blockDim.x + threadIdx.x;
    if (i < n) p[i] = 0.f;
}

__global__ void copy_kernel(float* __restrict__ dst, const float* __restrict__ src, int n) {
    int i = blockIdx.x * blockDim.x + threadIdx.x;
    if (i < n) dst[i] = src[i];
}

__global__ void deg_kernel(const int* __restrict__ src, float* __restrict__ deg, int E) {
    int i = blockIdx.x * blockDim.x + threadIdx.x;
    if (i < E) atomicAdd(&deg[src[i]], 1.f);
}

// ---------------- tf32 + fragment-major helpers ------------------------------
__device__ __forceinline__ unsigned f2tf(float f) {
    unsigned r;
    asm("cvt.rna.tf32.f32 %0, %1;" : "=r"(r) : "f"(f));
    return r;
}

__device__ __forceinline__ void mma_tf32(float c[4],
                                         unsigned a0, unsigned a1, unsigned a2, unsigned a3,
                                         unsigned b0, unsigned b1) {
    asm volatile(
        "mma.sync.aligned.m16n8k8.row.col.f32.tf32.tf32.f32 "
        "{%0,%1,%2,%3}, {%4,%5,%6,%7}, {%8,%9}, {%0,%1,%2,%3};"
        : "+f"(c[0]), "+f"(c[1]), "+f"(c[2]), "+f"(c[3])
        : "r"(a0), "r"(a1), "r"(a2), "r"(a3), "r"(b0), "r"(b1));
}

// ---- split LDG / STS for A chunks (128 rows x 32 k) -> 32 groups, stride 132
__device__ __forceinline__ void ldg_A(float4 v[4], const float* __restrict__ A,
                                      size_t lda, int row0, int M, int kglob0, int tid)
{
#pragma unroll
    for (int it = 0; it < 4; ++it) {
        int item = tid + it * 256;
        int row = item >> 3, q = item & 7;
        v[it] = make_float4(0.f, 0.f, 0.f, 0.f);
        if (row0 + row < M)
            v[it] = *(const float4*)(A + (size_t)(row0 + row) * lda + kglob0 + q * 4);
    }
}

__device__ __forceinline__ void sts_A(unsigned* __restrict__ As, const float4 v[4], int tid)
{
#pragma unroll
    for (int it = 0; it < 4; ++it) {
        int item = tid + it * 256;
        int row = item >> 3, q = item & 7;
        int g = ((row >> 4) << 2) + (q >> 1);
        int base = g * 132 + ((row & 7) << 4) + ((row >> 3) & 1) + ((q & 1) << 1);
        As[base + 0]  = f2tf(v[it].x);
        As[base + 4]  = f2tf(v[it].y);
        As[base + 8]  = f2tf(v[it].z);
        As[base + 12] = f2tf(v[it].w);
    }
}

// ---- split LDG / STS for B chunks (32 k x 128 n) -> 64 groups, stride 66
__device__ __forceinline__ void ldg_B(float4 v[4], const float* __restrict__ B,
                                      size_t ldb, int kglob0, int n0, int tid)
{
#pragma unroll
    for (int it = 0; it < 4; ++it) {
        int item = tid + it * 256;
        int k = item >> 5, q = item & 31;
        v[it] = *(const float4*)(B + (size_t)(kglob0 + k) * ldb + n0 + q * 4);
    }
}

__device__ __forceinline__ void sts_B(unsigned* __restrict__ Bs, const float4 v[4], int tid)
{
#pragma unroll
    for (int it = 0; it < 4; ++it) {
        int item = tid + it * 256;
        int k = item >> 5, q = item & 31;
        int gb = ((k >> 3) << 4) + (q >> 1);
        int base = gb * 66 + ((q & 1) << 5) + ((k & 3) << 1) + ((k >> 2) & 1);
        Bs[base + 0]  = f2tf(v[it].x);
        Bs[base + 8]  = f2tf(v[it].y);
        Bs[base + 16] = f2tf(v[it].z);
        Bs[base + 24] = f2tf(v[it].w);
    }
}

// one 32-k chunk of warp-tile 64x32 mma (4 mtiles x 4 ntiles)
__device__ __forceinline__ void mma_chunk(float acc[4][4][4],
                                          const unsigned* __restrict__ Af, int mg0, int gs, int gk0,
                                          const unsigned* __restrict__ Bs, int ng0, int lane)
{
#pragma unroll
    for (int kt = 0; kt < 4; ++kt) {
        uint4 a[4]; uint2 b[4];
#pragma unroll
        for (int mi = 0; mi < 4; ++mi)
            a[mi] = *(const uint4*)&Af[((mg0 + mi) * gs + gk0 + kt) * 132 + lane * 4];
#pragma unroll
        for (int ni = 0; ni < 4; ++ni)
            b[ni] = *(const uint2*)&Bs[((kt << 4) + ng0 + ni) * 66 + lane * 2];
#pragma unroll
        for (int mi = 0; mi < 4; ++mi)
#pragma unroll
            for (int ni = 0; ni < 4; ++ni)
                mma_tf32(acc[mi][ni], a[mi].x, a[mi].y, a[mi].z, a[mi].w,
                         b[ni].x, b[ni].y);
    }
}

#define ACC_ZERO(acc) \
    _Pragma("unroll") for (int mi = 0; mi < 4; ++mi) \
    _Pragma("unroll") for (int ni = 0; ni < 4; ++ni) \
    _Pragma("unroll") for (int j = 0; j < 4; ++j) acc[mi][ni][j] = 0.f;

// ---------------- fused edge MLP (tf32, 64x32 warp tiles, double-buffered) --
#define WB_WORDS (4 * 64 * 66)     // 16896 (= 128 groups * 132 for Cs)
#define CHUNK_WORDS (32 * 132)     // 4224
#define EDGE_SMEM ((WB_WORDS + 2 * CHUNK_WORDS + 256) * 4)
#define GEMM_SMEM ((4 * CHUNK_WORDS) * 4)

__global__ __launch_bounds__(256, 2)
void edge_mlp_tc(const float* __restrict__ hE,
                 const int* __restrict__ esrc,
                 const int* __restrict__ edst,
                 const float* __restrict__ XVs,
                 const float* __restrict__ XVd,
                 const float* __restrict__ W1a, const float* __restrict__ b1,
                 const float* __restrict__ W2,  const float* __restrict__ b2,
                 const float* __restrict__ W3,  const float* __restrict__ b3,
                 float* __restrict__ agg, int E)
{
    extern __shared__ unsigned smem_u[];
    unsigned* WB = smem_u;                  // W1a resident; later Cs
    unsigned* Asb[2] = { WB + WB_WORDS, WB + WB_WORDS + CHUNK_WORDS };
    int* s_src = (int*)(WB + WB_WORDS + 2 * CHUNK_WORDS);
    int* s_dst = s_src + 128;

    const int tid = threadIdx.x;
    const int lane = tid & 31;
    const int wid = tid >> 5;
    const int mrow0 = (wid >> 2) * 64;
    const int ncol0 = (wid & 3) * 32;
    const int mg0 = mrow0 >> 4;
    const int ng0 = ncol0 >> 3;
    const int lq = lane >> 2;
    const int lr = lane & 3;
    const int e0 = blockIdx.x * 128;

    if (tid < 128) {
        int e = e0 + tid;
        s_src[tid] = (e < E) ? esrc[e] : -1;
        s_dst[tid] = (e < E) ? edst[e] : -1;
    }

    float4 v[4];
    float acc[4][4][4];

    // ================= stage 1: hE @ W1a (W resident, A ping-pong) ==========
    ACC_ZERO(acc);
#pragma unroll
    for (int c = 0; c < 4; ++c) {
        ldg_B(v, W1a, HD, c * 32, 0, tid);
        sts_B(WB + c * CHUNK_WORDS, v, tid);
    }
    ldg_A(v, hE, HD, e0, E, 0, tid);
    sts_A(Asb[0], v, tid);
    __syncthreads();

#pragma unroll
    for (int kc = 0; kc < 4; ++kc) {
        if (kc < 3) ldg_A(v, hE, HD, e0, E, (kc + 1) * 32, tid);
        mma_chunk(acc, Asb[kc & 1], mg0, 4, 0, WB + kc * CHUNK_WORDS, ng0, lane);
        if (kc < 3) sts_A(Asb[(kc + 1) & 1], v, tid);
        __syncthreads();
    }

    unsigned* Cs = WB;   // alias — all W1a reads are done

    // prefetch W2 chunk 0 (lands while epilogue runs)
    ldg_B(v, W2, HD, 0, 0, tid);

    // epilogue 1: + b1 + XVs[src] + XVd[dst], relu, tf32 -> Cs fragment-major
#pragma unroll
    for (int ni = 0; ni < 4; ++ni) {
        int cb = ncol0 + ni * 8 + 2 * lr;
        float b10 = b1[cb], b11 = b1[cb + 1];
#pragma unroll
        for (int mi = 0; mi < 4; ++mi) {
#pragma unroll
            for (int h = 0; h < 2; ++h) {
                int r = mrow0 + mi * 16 + lq + h * 8;
                int ns = s_src[r], nd = s_dst[r];
                float v0 = 0.f, v1 = 0.f;
                if (ns >= 0) {
                    float2 xs = *(const float2*)(XVs + (size_t)ns * HD + cb);
                    float2 xd = *(const float2*)(XVd + (size_t)nd * HD + cb);
                    v0 = acc[mi][ni][h * 2 + 0] + b10 + xs.x + xd.x;
                    v1 = acc[mi][ni][h * 2 + 1] + b11 + xs.y + xd.y;
                }
#pragma unroll
                for (int e = 0; e < 2; ++e) {
                    int t = 2 * lr + e;
                    Cs[((mg0 + mi) * 16 + ng0 + ni) * 132
                       + ((lq * 4 + (t & 3)) << 2) + h + ((t >> 2) << 1)]
                        = f2tf(fmaxf(e ? v1 : v0, 0.f));
                }
            }
        }
    }
    sts_B(Asb[0], v, tid);
    __syncthreads();

    // ================= stage 2: C1 @ W2 (W ping-pong) =======================
    ACC_ZERO(acc);
#pragma unroll
    for (int kc = 0; kc < 4; ++kc) {
        if (kc < 3) ldg_B(v, W2, HD, (kc + 1) * 32, 0, tid);
        mma_chunk(acc, Cs, mg0, 16, kc * 4, Asb[kc & 1], ng0, lane);
        if (kc < 3) sts_B(Asb[(kc + 1) & 1], v, tid);
        __syncthreads();
    }

    // prefetch W3 chunk 0
    ldg_B(v, W3, HD, 0, 0, tid);

    // epilogue 2: + b2, relu, tf32 -> Cs (in place, own slots)
#pragma unroll
    for (int ni = 0; ni < 4; ++ni) {
        int cb = ncol0 + ni * 8 + 2 * lr;
        float b20 = b2[cb], b21 = b2[cb + 1];
#pragma unroll
        for (int mi = 0; mi < 4; ++mi) {
#pragma unroll
            for (int h = 0; h < 2; ++h) {
#pragma unroll
                for (int e = 0; e < 2; ++e) {
                    int t = 2 * lr + e;
                    float vv = acc[mi][ni][h * 2 + e] + (e ? b21 : b20);
                    Cs[((mg0 + mi) * 16 + ng0 + ni) * 132
                       + ((lq * 4 + (t & 3)) << 2) + h + ((t >> 2) << 1)]
                        = f2tf(fmaxf(vv, 0.f));
                }
            }
        }
    }
    sts_B(Asb[0], v, tid);
    __syncthreads();

    // ================= stage 3: C2 @ W3 =================
    ACC_ZERO(acc);
#pragma unroll
    for (int kc = 0; kc < 4; ++kc) {
        if (kc < 3) ldg_B(v, W3, HD, (kc + 1) * 32, 0, tid);
        mma_chunk(acc, Cs, mg0, 16, kc * 4, Asb[kc & 1], ng0, lane);
        if (kc < 3) sts_B(Asb[(kc + 1) & 1], v, tid);
        __syncthreads();
    }

    // epilogue 3: + b3, stage f32 row-major (pitch 132) into Cs for scatter
    float* CsF = (float*)Cs;
#pragma unroll
    for (int ni = 0; ni < 4; ++ni) {
        int cb = ncol0 + ni * 8 + 2 * lr;
        float b30 = b3[cb], b31 = b3[cb + 1];
#pragma unroll
        for (int mi = 0; mi < 4; ++mi) {
#pragma unroll
            for (int h = 0; h < 2; ++h) {
                int r = mrow0 + mi * 16 + lq + h * 8;
                CsF[r * 132 + cb]     = acc[mi][ni][h * 2 + 0] + b30;
                CsF[r * 132 + cb + 1] = acc[mi][ni][h * 2 + 1] + b31;
            }
        }
    }
    __syncthreads();

    // cooperative vector scatter: 128 rows x 32 float4
    for (int item = tid; item < 128 * 32; item += 256) {
        int row = item >> 5, q = item & 31;
        int node = s_src[row];
        if (node >= 0) {
            const float4 vv = *(const float4*)(CsF + row * 132 + q * 4);
            float* p = agg + (size_t)node * HD + q * 4;
            asm volatile("red.global.add.v4.f32 [%0], {%1,%2,%3,%4};"
                         :: "l"(p), "f"(vv.x), "f"(vv.y), "f"(vv.z), "f"(vv.w)
                         : "memory");
        }
    }
}

// ---------------- tf32 node GEMM (128x128 tile, double-buffered) ------------
// epi 0: relu(A@B + bias); epi 1: A@B + bias + res; epi 2: A@B
// blockIdx.z selects (B,C) or (B2,C2) for the fused pre-GEMM pair
__global__ __launch_bounds__(256, 2)
void gemm_tc(const float* __restrict__ A, const float* __restrict__ B,
             const float* __restrict__ B2,
             const float* __restrict__ bias, const float* __restrict__ res,
             float* __restrict__ C, float* __restrict__ C2,
             int M, int N, int K, int epi)
{
    extern __shared__ unsigned smem_u[];
    unsigned* Asb[2] = { smem_u, smem_u + CHUNK_WORDS };
    unsigned* Bsb[2] = { smem_u + 2 * CHUNK_WORDS, smem_u + 3 * CHUNK_WORDS };

    const int tid = threadIdx.x;
    const int lane = tid & 31;
    const int wid = tid >> 5;
    const int mrow0 = (wid >> 2) * 64;
    const int ncol0 = (wid & 3) * 32;
    const int mg0 = mrow0 >> 4;
    const int ng0 = ncol0 >> 3;
    const int lq = lane >> 2;
    const int lr = lane & 3;
    const int m0 = blockIdx.y * 128, n0 = blockIdx.x * 128;
    if (blockIdx.z) { B = B2; C = C2; }

    float4 va[4], vb[4];
    float acc[4][4][4];
    ACC_ZERO(acc);

    const int nkc = K / 32;
    ldg_A(va, A, K, m0, M, 0, tid);
    ldg_B(vb, B, N, 0, n0, tid);
    sts_A(Asb[0], va, tid);
    sts_B(Bsb[0], vb, tid);
    __syncthreads();

    for (int kc = 0; kc < nkc; ++kc) {
        if (kc + 1 < nkc) {
            ldg_A(va, A, K, m0, M, (kc + 1) * 32, tid);
            ldg_B(vb, B, N, (kc + 1) * 32, n0, tid);
        }
        mma_chunk(acc, Asb[kc & 1], mg0, 4, 0, Bsb[kc & 1], ng0, lane);
        if (kc + 1 < nkc) {
            sts_A(Asb[(kc + 1) & 1], va, tid);
            sts_B(Bsb[(kc + 1) & 1], vb, tid);
        }
        __syncthreads();
    }

#pragma unroll
    for (int ni = 0; ni < 4; ++ni) {
        int c = n0 + ncol0 + ni * 8 + 2 * lr;
        float bb0 = (epi == 2) ? 0.f : bias[c];
        float bb1 = (epi == 2) ? 0.f : bias[c + 1];
#pragma unroll
        for (int mi = 0; mi < 4; ++mi) {
#pragma unroll
            for (int h = 0; h < 2; ++h) {
                int r = m0 + mrow0 + mi * 16 + lq + h * 8;
                if (r < M) {
                    float v0 = acc[mi][ni][h * 2 + 0] + bb0;
                    float v1 = acc[mi][ni][h * 2 + 1] + bb1;
                    if (epi == 0) { v0 = fmaxf(v0, 0.f); v1 = fmaxf(v1, 0.f); }
                    else if (epi == 1) {
                        v0 += res[(size_t)r * N + c];
                        v1 += res[(size_t)r * N + c + 1];
                    }
                    C[(size_t)r * N + c]     = v0;
                    C[(size_t)r * N + c + 1] = v1;
                }
            }
        }
    }
}

// ---------------- layernorm kernels (one warp per node, H=128) -------------
__device__ __forceinline__ float warp_sum(float v) {
#pragma unroll
    for (int o = 16; o > 0; o >>= 1) v += __shfl_xor_sync(0xffffffffu, v, o);
    return v;
}

__global__ void agg_ln_kernel(float* __restrict__ hV, const float* __restrict__ agg,
                              const float* __restrict__ deg,
                              const float* __restrict__ g, const float* __restrict__ b,
                              int N)
{
    int warp = (blockIdx.x * blockDim.x + threadIdx.x) >> 5;
    int lane = threadIdx.x & 31;
    if (warp >= N) return;
    float d = fmaxf(deg[warp], 1.f);
    float x[4];
#pragma unroll
    for (int j = 0; j < 4; j++) {
        int c = j * 32 + lane;
        x[j] = hV[(size_t)warp * HD + c] + agg[(size_t)warp * HD + c] / d;
    }
    float s = warp_sum(x[0] + x[1] + x[2] + x[3]);
    float mu = s * (1.f / HD);
    float ss = warp_sum(x[0]*x[0] + x[1]*x[1] + x[2]*x[2] + x[3]*x[3]);
    float var = ss * (1.f / HD) - mu * mu;
    float inv = rsqrtf(var + 1e-5f);
#pragma unroll
    for (int j = 0; j < 4; j++) {
        int c = j * 32 + lane;
        hV[(size_t)warp * HD + c] = (x[j] - mu) * inv * g[c] + b[c];
    }
}

__global__ void ln_kernel(const float* __restrict__ x, float* __restrict__ out,
                          const float* __restrict__ g, const float* __restrict__ b,
                          int N)
{
    int warp = (blockIdx.x * blockDim.x + threadIdx.x) >> 5;
    int lane = threadIdx.x & 31;
    if (warp >= N) return;
    float v[4];
#pragma unroll
    for (int j = 0; j < 4; j++) v[j] = x[(size_t)warp * HD + j * 32 + lane];
    float s = warp_sum(v[0] + v[1] + v[2] + v[3]);
    float mu = s * (1.f / HD);
    float ss = warp_sum(v[0]*v[0] + v[1]*v[1] + v[2]*v[2] + v[3]*v[3]);
    float var = ss * (1.f / HD) - mu * mu;
    float inv = rsqrtf(var + 1e-5f);
#pragma unroll
    for (int j = 0; j < 4; j++) {
        int c = j * 32 + lane;
        out[(size_t)warp * HD + c] = (v[j] - mu) * inv * g[c] + b[c];
    }
}

// ---------------- pooling / heads ------------------------------------------
__global__ void pool_kernel(const float* __restrict__ hV, const int* __restrict__ batch_id,
                            float* __restrict__ pool, float* __restrict__ pcnt, int N)
{
    int i = blockIdx.x * blockDim.x + threadIdx.x;
    if (i < N * HD) {
        int n = i >> 7, c = i & 127;
        atomicAdd(&pool[batch_id[n] * HD + c], hV[i]);
    }
    if (i < N) atomicAdd(&pcnt[batch_id[i]], 1.f);
}

__global__ void head_kernel(const float* __restrict__ pool, const float* __restrict__ pcnt,
                            const float* __restrict__ P1, const float* __restrict__ P2,
                            const float* __restrict__ p2b, float* __restrict__ out)
{
    __shared__ float embs[NB * HD];
    __shared__ float t1[NB * HD];
    int tid = threadIdx.x;
    for (int i = tid; i < NB * HD; i += blockDim.x) {
        int bb = i >> 7;
        embs[i] = pool[i] / fmaxf(pcnt[bb], 1.f);
    }
    __syncthreads();
    for (int i = tid; i < NB * HD; i += blockDim.x) {
        int bb = i >> 7, j = i & 127;
        float s = 0.f;
        for (int k = 0; k < HD; k++) s += embs[bb * HD + k] * P1[k * HD + j];
        t1[i] = fmaxf(s, 0.f);
    }
    __syncthreads();
    for (int i = tid; i < NB * HD; i += blockDim.x) {
        int bb = i >> 7, j = i & 127;
        float s = p2b[j];
        for (int k = 0; k < HD; k++) s += t1[bb * HD + k] * P2[k * HD + j];
        out[i] = s;
    }
}

__global__ void logits_kernel(const float* __restrict__ hV, const int* __restrict__ S,
                              const float* __restrict__ R, const float* __restrict__ rb,
                              float* __restrict__ out, int N)
{
    __shared__ float Rs[HD * NV];
    __shared__ float rbs[NV];
    int tid = threadIdx.x;
    for (int i = tid; i < HD * NV; i += blockDim.x) Rs[i] = R[i];
    if (tid < NV) rbs[tid] = rb[tid];
    __syncthreads();
    int n = blockIdx.x * blockDim.x + tid;
    if (n < N) {
        float a0 = rbs[0], a1 = rbs[1], a2 = rbs[2], a3 = rbs[3];
        const float* h = hV + (size_t)n * HD;
#pragma unroll 8
        for (int k = 0; k < HD; k++) {
            float hv = h[k];
            a0 += hv * Rs[k * NV + 0];
            a1 += hv * Rs[k * NV + 1];
            a2 += hv * Rs[k * NV + 2];
            a3 += hv * Rs[k * NV + 3];
        }
        out[(size_t)n * NV + 0] = a0;
        out[(size_t)n * NV + 1] = a1;
        out[(size_t)n * NV + 2] = a2;
        out[(size_t)n * NV + 3] = a3;
        out[(size_t)N * NV + n] = (float)S[n];
    }
}

// ---------------- launch ----------------------------------------------------
extern "C" void kernel_launch(void* const* d_in, const int* in_sizes, int n_in,
                              void* d_out, int out_size)
{
    const float* h_V  = (const float*)d_in[0];
    const float* h_E  = (const float*)d_in[1];
    const int*   Eidx = (const int*)d_in[2];
    const int*   bid  = (const int*)d_in[3];
    const int*   S    = (const int*)d_in[4];
    const float* W1   = (const float*)d_in[5];
    const float* b1   = (const float*)d_in[6];
    const float* W2   = (const float*)d_in[7];
    const float* b2   = (const float*)d_in[8];
    const float* W3   = (const float*)d_in[9];
    const float* b3   = (const float*)d_in[10];
    const float* ln1g = (const float*)d_in[11];
    const float* ln1b = (const float*)d_in[12];
    const float* Wi   = (const float*)d_in[13];
    const float* bi   = (const float*)d_in[14];
    const float* Wo   = (const float*)d_in[15];
    const float* bo   = (const float*)d_in[16];
    const float* ln2g = (const float*)d_in[17];
    const float* ln2b = (const float*)d_in[18];
    const float* P1   = (const float*)d_in[19];
    const float* P2   = (const float*)d_in[20];
    const float* p2b  = (const float*)d_in[21];
    const float* R    = (const float*)d_in[22];
    const float* rb   = (const float*)d_in[23];

    const int N = in_sizes[0] / HD;
    const int E = in_sizes[2] / 2;
    const int* esrc = Eidx;
    const int* edst = Eidx + E;

    float *p_hV, *p_agg, *p_tmp, *p_ffn, *p_xvs, *p_xvd, *p_deg, *p_pool, *p_pcnt;
    cudaGetSymbolAddress((void**)&p_hV,   g_hV);
    cudaGetSymbolAddress((void**)&p_agg,  g_agg);
    cudaGetSymbolAddress((void**)&p_tmp,  g_tmp);
    cudaGetSymbolAddress((void**)&p_ffn,  g_ffn);
    cudaGetSymbolAddress((void**)&p_xvs,  g_xvs);
    cudaGetSymbolAddress((void**)&p_xvd,  g_xvd);
    cudaGetSymbolAddress((void**)&p_deg,  g_deg);
    cudaGetSymbolAddress((void**)&p_pool, g_pool);
    cudaGetSymbolAddress((void**)&p_pcnt, g_pcnt);

    cudaFuncSetAttribute(edge_mlp_tc,
                         cudaFuncAttributeMaxDynamicSharedMemorySize, EDGE_SMEM);
    cudaFuncSetAttribute(gemm_tc,
                         cudaFuncAttributeMaxDynamicSharedMemorySize, GEMM_SMEM);

    copy_kernel<<<(N * HD + 255) / 256, 256>>>(p_hV, h_V, N * HD);

    zero_kernel<<<(N + 255) / 256, 256>>>(p_deg, N);
    deg_kernel<<<(E + 255) / 256, 256>>>(esrc, p_deg, E);

    const int edge_grid = (E + 127) / 128;
    const int mtiles = (N + 127) / 128;

    for (int l = 0; l < NL; ++l) {
        const float* W1l = W1 + (size_t)l * 3 * HD * HD;
        gemm_tc<<<dim3(1, mtiles, 2), 256, GEMM_SMEM>>>(
            p_hV, W1l + (size_t)HD * HD, W1l + (size_t)2 * HD * HD,
            nullptr, nullptr, p_xvs, p_xvd, N, HD, HD, 2);

        zero_kernel<<<(N * HD + 255) / 256, 256>>>(p_agg, N * HD);
        edge_mlp_tc<<<edge_grid, 256, EDGE_SMEM>>>(
            h_E, esrc, edst, p_xvs, p_xvd,
            W1l, b1 + (size_t)l * HD,
            W2 + (size_t)l * HD * HD, b2 + (size_t)l * HD,
            W3 + (size_t)l * HD * HD, b3 + (size_t)l * HD,
            p_agg, E);
        agg_ln_kernel<<<(N + 7) / 8, 256>>>(p_hV, p_agg, p_deg,
                                            ln1g + (size_t)l * HD, ln1b + (size_t)l * HD, N);
        gemm_tc<<<dim3(4, mtiles, 1), 256, GEMM_SMEM>>>(
            p_hV, Wi + (size_t)l * HD * 4 * HD, nullptr,
            bi + (size_t)l * 4 * HD, nullptr, p_ffn, nullptr, N, 4 * HD, HD, 0);
        gemm_tc<<<dim3(1, mtiles, 1), 256, GEMM_SMEM>>>(
            p_ffn, Wo + (size_t)l * 4 * HD * HD, nullptr,
            bo + (size_t)l * HD, p_hV, p_tmp, nullptr, N, HD, 4 * HD, 1);
        ln_kernel<<<(N + 7) / 8, 256>>>(p_tmp, p_hV,
                                        ln2g + (size_t)l * HD, ln2b + (size_t)l * HD, N);
    }

    zero_kernel<<<(NB * HD + 255) / 256, 256>>>(p_pool, NB * HD);
    zero_kernel<<<1, 32>>>(p_pcnt, NB);
    pool_kernel<<<(N * HD + 255) / 256, 256>>>(p_hV, bid, p_pool, p_pcnt, N);

    float* out = (float*)d_out;
    head_kernel<<<1, 256>>>(p_pool, p_pcnt, P1, P2, p2b,
                            out + (size_t)N * NV + N);
    logits_kernel<<<(N + 255) / 256, 256>>>(p_hV, S, R, rb, out, N);
}

// round 8
// speedup vs baseline: 1.3890x; 1.1397x over previous
#include <cuda_runtime.h>
#include <math.h>

#define HD 128
#define NB 16     // batches
#define NV 4      // vocab
#define NL 6      // layers
#define MAXN 20000
#define MAXE 600000

// ---------------- scratch (static device allocs; cudaMalloc is banned) -----
__device__ float g_hV[MAXN * HD];
__device__ float g_agg[MAXN * HD];
__device__ float g_tmp[MAXN * HD];
__device__ float g_ffn[MAXN * 4 * HD];
__device__ float g_xvs[MAXN * HD];      // h_V @ W1_src ; later T = agg @ W3
__device__ float g_xvd[MAXN * HD];
__device__ float g_deg[MAXN];
__device__ float g_pool[NB * HD];
__device__ float g_pcnt[NB];

// ---------------- tiny utility kernels -------------------------------------
__global__ void zero_kernel(float* __restrict__ p, int n) {
    int i = blockIdx.x * blockDim.x + threadIdx.x;
    if (i < n) p[i] = 0.f;
}

__global__ void copy_kernel(float* __restrict__ dst, const float* __restrict__ src, int n) {
    int i = blockIdx.x * blockDim.x + threadIdx.x;
    if (i < n) dst[i] = src[i];
}

__global__ void deg_kernel(const int* __restrict__ src, float* __restrict__ deg, int E) {
    int i = blockIdx.x * blockDim.x + threadIdx.x;
    if (i < E) atomicAdd(&deg[src[i]], 1.f);
}

// ---------------- tf32 + fragment-major helpers ------------------------------
__device__ __forceinline__ unsigned f2tf(float f) {
    unsigned r;
    asm("cvt.rna.tf32.f32 %0, %1;" : "=r"(r) : "f"(f));
    return r;
}

__device__ __forceinline__ void mma_tf32(float c[4],
                                         unsigned a0, unsigned a1, unsigned a2, unsigned a3,
                                         unsigned b0, unsigned b1) {
    asm volatile(
        "mma.sync.aligned.m16n8k8.row.col.f32.tf32.tf32.f32 "
        "{%0,%1,%2,%3}, {%4,%5,%6,%7}, {%8,%9}, {%0,%1,%2,%3};"
        : "+f"(c[0]), "+f"(c[1]), "+f"(c[2]), "+f"(c[3])
        : "r"(a0), "r"(a1), "r"(a2), "r"(a3), "r"(b0), "r"(b1));
}

// ---- split LDG / STS for A chunks (128 rows x 32 k) -> 32 groups, stride 132
__device__ __forceinline__ void ldg_A(float4 v[4], const float* __restrict__ A,
                                      size_t lda, int row0, int M, int kglob0, int tid)
{
#pragma unroll
    for (int it = 0; it < 4; ++it) {
        int item = tid + it * 256;
        int row = item >> 3, q = item & 7;
        v[it] = make_float4(0.f, 0.f, 0.f, 0.f);
        if (row0 + row < M)
            v[it] = *(const float4*)(A + (size_t)(row0 + row) * lda + kglob0 + q * 4);
    }
}

__device__ __forceinline__ void sts_A(unsigned* __restrict__ As, const float4 v[4], int tid)
{
#pragma unroll
    for (int it = 0; it < 4; ++it) {
        int item = tid + it * 256;
        int row = item >> 3, q = item & 7;
        int g = ((row >> 4) << 2) + (q >> 1);
        int base = g * 132 + ((row & 7) << 4) + ((row >> 3) & 1) + ((q & 1) << 1);
        As[base + 0]  = f2tf(v[it].x);
        As[base + 4]  = f2tf(v[it].y);
        As[base + 8]  = f2tf(v[it].z);
        As[base + 12] = f2tf(v[it].w);
    }
}

// ---- split LDG / STS for B chunks (32 k x 128 n) -> 64 groups, stride 66
__device__ __forceinline__ void ldg_B(float4 v[4], const float* __restrict__ B,
                                      size_t ldb, int kglob0, int n0, int tid)
{
#pragma unroll
    for (int it = 0; it < 4; ++it) {
        int item = tid + it * 256;
        int k = item >> 5, q = item & 31;
        v[it] = *(const float4*)(B + (size_t)(kglob0 + k) * ldb + n0 + q * 4);
    }
}

__device__ __forceinline__ void sts_B(unsigned* __restrict__ Bs, const float4 v[4], int tid)
{
#pragma unroll
    for (int it = 0; it < 4; ++it) {
        int item = tid + it * 256;
        int k = item >> 5, q = item & 31;
        int gb = ((k >> 3) << 4) + (q >> 1);
        int base = gb * 66 + ((q & 1) << 5) + ((k & 3) << 1) + ((k >> 2) & 1);
        Bs[base + 0]  = f2tf(v[it].x);
        Bs[base + 8]  = f2tf(v[it].y);
        Bs[base + 16] = f2tf(v[it].z);
        Bs[base + 24] = f2tf(v[it].w);
    }
}

// one 32-k chunk of warp-tile 64x32 mma (4 mtiles x 4 ntiles)
__device__ __forceinline__ void mma_chunk(float acc[4][4][4],
                                          const unsigned* __restrict__ Af, int mg0, int gs, int gk0,
                                          const unsigned* __restrict__ Bs, int ng0, int lane)
{
#pragma unroll
    for (int kt = 0; kt < 4; ++kt) {
        uint4 a[4]; uint2 b[4];
#pragma unroll
        for (int mi = 0; mi < 4; ++mi)
            a[mi] = *(const uint4*)&Af[((mg0 + mi) * gs + gk0 + kt) * 132 + lane * 4];
#pragma unroll
        for (int ni = 0; ni < 4; ++ni)
            b[ni] = *(const uint2*)&Bs[((kt << 4) + ng0 + ni) * 66 + lane * 2];
#pragma unroll
        for (int mi = 0; mi < 4; ++mi)
#pragma unroll
            for (int ni = 0; ni < 4; ++ni)
                mma_tf32(acc[mi][ni], a[mi].x, a[mi].y, a[mi].z, a[mi].w,
                         b[ni].x, b[ni].y);
    }
}

#define ACC_ZERO(acc) \
    _Pragma("unroll") for (int mi = 0; mi < 4; ++mi) \
    _Pragma("unroll") for (int ni = 0; ni < 4; ++ni) \
    _Pragma("unroll") for (int j = 0; j < 4; ++j) acc[mi][ni][j] = 0.f;

// ---------------- fused edge MLP (2 stages; W3 hoisted to node GEMM) --------
// Stage 1: C1 = relu(hE @ W1a + XVs[src] + XVd[dst] + b1)    (K = 128)
// Stage 2: C2 = relu(C1 @ W2 + b2) ; red.v4 scatter C2 into agg[src]
#define WB_WORDS (4 * 64 * 66)     // 16896 (= 128 groups * 132 for Cs)
#define CHUNK_WORDS (32 * 132)     // 4224
#define EDGE_SMEM ((WB_WORDS + 2 * CHUNK_WORDS + 256) * 4)
#define GEMM_SMEM ((4 * CHUNK_WORDS) * 4)

__global__ __launch_bounds__(256, 2)
void edge_mlp_tc(const float* __restrict__ hE,
                 const int* __restrict__ esrc,
                 const int* __restrict__ edst,
                 const float* __restrict__ XVs,
                 const float* __restrict__ XVd,
                 const float* __restrict__ W1a, const float* __restrict__ b1,
                 const float* __restrict__ W2,  const float* __restrict__ b2,
                 float* __restrict__ agg, int E)
{
    extern __shared__ unsigned smem_u[];
    unsigned* WB = smem_u;                  // W1a resident; later Cs
    unsigned* Asb[2] = { WB + WB_WORDS, WB + WB_WORDS + CHUNK_WORDS };
    int* s_src = (int*)(WB + WB_WORDS + 2 * CHUNK_WORDS);
    int* s_dst = s_src + 128;

    const int tid = threadIdx.x;
    const int lane = tid & 31;
    const int wid = tid >> 5;
    const int mrow0 = (wid >> 2) * 64;
    const int ncol0 = (wid & 3) * 32;
    const int mg0 = mrow0 >> 4;
    const int ng0 = ncol0 >> 3;
    const int lq = lane >> 2;
    const int lr = lane & 3;
    const int e0 = blockIdx.x * 128;

    if (tid < 128) {
        int e = e0 + tid;
        s_src[tid] = (e < E) ? esrc[e] : -1;
        s_dst[tid] = (e < E) ? edst[e] : -1;
    }

    float4 v[4];
    float acc[4][4][4];

    // ================= stage 1: hE @ W1a (W resident, A ping-pong) ==========
    ACC_ZERO(acc);
#pragma unroll
    for (int c = 0; c < 4; ++c) {
        ldg_B(v, W1a, HD, c * 32, 0, tid);
        sts_B(WB + c * CHUNK_WORDS, v, tid);
    }
    ldg_A(v, hE, HD, e0, E, 0, tid);
    sts_A(Asb[0], v, tid);
    __syncthreads();

#pragma unroll
    for (int kc = 0; kc < 4; ++kc) {
        if (kc < 3) ldg_A(v, hE, HD, e0, E, (kc + 1) * 32, tid);
        mma_chunk(acc, Asb[kc & 1], mg0, 4, 0, WB + kc * CHUNK_WORDS, ng0, lane);
        if (kc < 3) sts_A(Asb[(kc + 1) & 1], v, tid);
        __syncthreads();
    }

    unsigned* Cs = WB;   // alias — all W1a reads are done

    // prefetch W2 chunk 0 (lands while epilogue runs)
    ldg_B(v, W2, HD, 0, 0, tid);

    // epilogue 1: + b1 + XVs[src] + XVd[dst], relu, tf32 -> Cs fragment-major
#pragma unroll
    for (int ni = 0; ni < 4; ++ni) {
        int cb = ncol0 + ni * 8 + 2 * lr;
        float b10 = b1[cb], b11 = b1[cb + 1];
#pragma unroll
        for (int mi = 0; mi < 4; ++mi) {
#pragma unroll
            for (int h = 0; h < 2; ++h) {
                int r = mrow0 + mi * 16 + lq + h * 8;
                int ns = s_src[r], nd = s_dst[r];
                float v0 = 0.f, v1 = 0.f;
                if (ns >= 0) {
                    float2 xs = *(const float2*)(XVs + (size_t)ns * HD + cb);
                    float2 xd = *(const float2*)(XVd + (size_t)nd * HD + cb);
                    v0 = acc[mi][ni][h * 2 + 0] + b10 + xs.x + xd.x;
                    v1 = acc[mi][ni][h * 2 + 1] + b11 + xs.y + xd.y;
                }
#pragma unroll
                for (int e = 0; e < 2; ++e) {
                    int t = 2 * lr + e;
                    Cs[((mg0 + mi) * 16 + ng0 + ni) * 132
                       + ((lq * 4 + (t & 3)) << 2) + h + ((t >> 2) << 1)]
                        = f2tf(fmaxf(e ? v1 : v0, 0.f));
                }
            }
        }
    }
    sts_B(Asb[0], v, tid);
    __syncthreads();

    // ================= stage 2: C1 @ W2 (W ping-pong) =======================
    ACC_ZERO(acc);
#pragma unroll
    for (int kc = 0; kc < 4; ++kc) {
        if (kc < 3) ldg_B(v, W2, HD, (kc + 1) * 32, 0, tid);
        mma_chunk(acc, Cs, mg0, 16, kc * 4, Asb[kc & 1], ng0, lane);
        if (kc < 3) sts_B(Asb[(kc + 1) & 1], v, tid);
        __syncthreads();
    }

    // epilogue 2 (final): relu(acc + b2) as f32 row-major into Cs for scatter
    float* CsF = (float*)Cs;
#pragma unroll
    for (int ni = 0; ni < 4; ++ni) {
        int cb = ncol0 + ni * 8 + 2 * lr;
        float b20 = b2[cb], b21 = b2[cb + 1];
#pragma unroll
        for (int mi = 0; mi < 4; ++mi) {
#pragma unroll
            for (int h = 0; h < 2; ++h) {
                int r = mrow0 + mi * 16 + lq + h * 8;
                CsF[r * 132 + cb]     = fmaxf(acc[mi][ni][h * 2 + 0] + b20, 0.f);
                CsF[r * 132 + cb + 1] = fmaxf(acc[mi][ni][h * 2 + 1] + b21, 0.f);
            }
        }
    }
    __syncthreads();

    // cooperative vector scatter of relu(C2): 128 rows x 32 float4
    for (int item = tid; item < 128 * 32; item += 256) {
        int row = item >> 5, q = item & 31;
        int node = s_src[row];
        if (node >= 0) {
            const float4 vv = *(const float4*)(CsF + row * 132 + q * 4);
            float* p = agg + (size_t)node * HD + q * 4;
            asm volatile("red.global.add.v4.f32 [%0], {%1,%2,%3,%4};"
                         :: "l"(p), "f"(vv.x), "f"(vv.y), "f"(vv.z), "f"(vv.w)
                         : "memory");
        }
    }
}

// ---------------- tf32 node GEMM (128x128 tile, double-buffered) ------------
// epi 0: relu(A@B + bias); epi 1: A@B + bias + res; epi 2: A@B
// blockIdx.z selects (B,C) or (B2,C2) for the fused pre-GEMM pair
__global__ __launch_bounds__(256, 2)
void gemm_tc(const float* __restrict__ A, const float* __restrict__ B,
             const float* __restrict__ B2,
             const float* __restrict__ bias, const float* __restrict__ res,
             float* __restrict__ C, float* __restrict__ C2,
             int M, int N, int K, int epi)
{
    extern __shared__ unsigned smem_u[];
    unsigned* Asb[2] = { smem_u, smem_u + CHUNK_WORDS };
    unsigned* Bsb[2] = { smem_u + 2 * CHUNK_WORDS, smem_u + 3 * CHUNK_WORDS };

    const int tid = threadIdx.x;
    const int lane = tid & 31;
    const int wid = tid >> 5;
    const int mrow0 = (wid >> 2) * 64;
    const int ncol0 = (wid & 3) * 32;
    const int mg0 = mrow0 >> 4;
    const int ng0 = ncol0 >> 3;
    const int lq = lane >> 2;
    const int lr = lane & 3;
    const int m0 = blockIdx.y * 128, n0 = blockIdx.x * 128;
    if (blockIdx.z) { B = B2; C = C2; }

    float4 va[4], vb[4];
    float acc[4][4][4];
    ACC_ZERO(acc);

    const int nkc = K / 32;
    ldg_A(va, A, K, m0, M, 0, tid);
    ldg_B(vb, B, N, 0, n0, tid);
    sts_A(Asb[0], va, tid);
    sts_B(Bsb[0], vb, tid);
    __syncthreads();

    for (int kc = 0; kc < nkc; ++kc) {
        if (kc + 1 < nkc) {
            ldg_A(va, A, K, m0, M, (kc + 1) * 32, tid);
            ldg_B(vb, B, N, (kc + 1) * 32, n0, tid);
        }
        mma_chunk(acc, Asb[kc & 1], mg0, 4, 0, Bsb[kc & 1], ng0, lane);
        if (kc + 1 < nkc) {
            sts_A(Asb[(kc + 1) & 1], va, tid);
            sts_B(Bsb[(kc + 1) & 1], vb, tid);
        }
        __syncthreads();
    }

#pragma unroll
    for (int ni = 0; ni < 4; ++ni) {
        int c = n0 + ncol0 + ni * 8 + 2 * lr;
        float bb0 = (epi == 2) ? 0.f : bias[c];
        float bb1 = (epi == 2) ? 0.f : bias[c + 1];
#pragma unroll
        for (int mi = 0; mi < 4; ++mi) {
#pragma unroll
            for (int h = 0; h < 2; ++h) {
                int r = m0 + mrow0 + mi * 16 + lq + h * 8;
                if (r < M) {
                    float v0 = acc[mi][ni][h * 2 + 0] + bb0;
                    float v1 = acc[mi][ni][h * 2 + 1] + bb1;
                    if (epi == 0) { v0 = fmaxf(v0, 0.f); v1 = fmaxf(v1, 0.f); }
                    else if (epi == 1) {
                        v0 += res[(size_t)r * N + c];
                        v1 += res[(size_t)r * N + c + 1];
                    }
                    C[(size_t)r * N + c]     = v0;
                    C[(size_t)r * N + c + 1] = v1;
                }
            }
        }
    }
}

// ---------------- layernorm kernels (one warp per node, H=128) -------------
__device__ __forceinline__ float warp_sum(float v) {
#pragma unroll
    for (int o = 16; o > 0; o >>= 1) v += __shfl_xor_sync(0xffffffffu, v, o);
    return v;
}

// hV = LN(hV + T/deg + b3) in place   (T = agg @ W3)
__global__ void agg_ln_kernel(float* __restrict__ hV, const float* __restrict__ T,
                              const float* __restrict__ deg, const float* __restrict__ b3,
                              const float* __restrict__ g, const float* __restrict__ b,
                              int N)
{
    int warp = (blockIdx.x * blockDim.x + threadIdx.x) >> 5;
    int lane = threadIdx.x & 31;
    if (warp >= N) return;
    float d = fmaxf(deg[warp], 1.f);
    float x[4];
#pragma unroll
    for (int j = 0; j < 4; j++) {
        int c = j * 32 + lane;
        x[j] = hV[(size_t)warp * HD + c] + T[(size_t)warp * HD + c] / d + b3[c];
    }
    float s = warp_sum(x[0] + x[1] + x[2] + x[3]);
    float mu = s * (1.f / HD);
    float ss = warp_sum(x[0]*x[0] + x[1]*x[1] + x[2]*x[2] + x[3]*x[3]);
    float var = ss * (1.f / HD) - mu * mu;
    float inv = rsqrtf(var + 1e-5f);
#pragma unroll
    for (int j = 0; j < 4; j++) {
        int c = j * 32 + lane;
        hV[(size_t)warp * HD + c] = (x[j] - mu) * inv * g[c] + b[c];
    }
}

__global__ void ln_kernel(const float* __restrict__ x, float* __restrict__ out,
                          const float* __restrict__ g, const float* __restrict__ b,
                          int N)
{
    int warp = (blockIdx.x * blockDim.x + threadIdx.x) >> 5;
    int lane = threadIdx.x & 31;
    if (warp >= N) return;
    float v[4];
#pragma unroll
    for (int j = 0; j < 4; j++) v[j] = x[(size_t)warp * HD + j * 32 + lane];
    float s = warp_sum(v[0] + v[1] + v[2] + v[3]);
    float mu = s * (1.f / HD);
    float ss = warp_sum(v[0]*v[0] + v[1]*v[1] + v[2]*v[2] + v[3]*v[3]);
    float var = ss * (1.f / HD) - mu * mu;
    float inv = rsqrtf(var + 1e-5f);
#pragma unroll
    for (int j = 0; j < 4; j++) {
        int c = j * 32 + lane;
        out[(size_t)warp * HD + c] = (v[j] - mu) * inv * g[c] + b[c];
    }
}

// ---------------- pooling / heads ------------------------------------------
__global__ void pool_kernel(const float* __restrict__ hV, const int* __restrict__ batch_id,
                            float* __restrict__ pool, float* __restrict__ pcnt, int N)
{
    int i = blockIdx.x * blockDim.x + threadIdx.x;
    if (i < N * HD) {
        int n = i >> 7, c = i & 127;
        atomicAdd(&pool[batch_id[n] * HD + c], hV[i]);
    }
    if (i < N) atomicAdd(&pcnt[batch_id[i]], 1.f);
}

__global__ void head_kernel(const float* __restrict__ pool, const float* __restrict__ pcnt,
                            const float* __restrict__ P1, const float* __restrict__ P2,
                            const float* __restrict__ p2b, float* __restrict__ out)
{
    __shared__ float embs[NB * HD];
    __shared__ float t1[NB * HD];
    int tid = threadIdx.x;
    for (int i = tid; i < NB * HD; i += blockDim.x) {
        int bb = i >> 7;
        embs[i] = pool[i] / fmaxf(pcnt[bb], 1.f);
    }
    __syncthreads();
    for (int i = tid; i < NB * HD; i += blockDim.x) {
        int bb = i >> 7, j = i & 127;
        float s = 0.f;
        for (int k = 0; k < HD; k++) s += embs[bb * HD + k] * P1[k * HD + j];
        t1[i] = fmaxf(s, 0.f);
    }
    __syncthreads();
    for (int i = tid; i < NB * HD; i += blockDim.x) {
        int bb = i >> 7, j = i & 127;
        float s = p2b[j];
        for (int k = 0; k < HD; k++) s += t1[bb * HD + k] * P2[k * HD + j];
        out[i] = s;
    }
}

__global__ void logits_kernel(const float* __restrict__ hV, const int* __restrict__ S,
                              const float* __restrict__ R, const float* __restrict__ rb,
                              float* __restrict__ out, int N)
{
    __shared__ float Rs[HD * NV];
    __shared__ float rbs[NV];
    int tid = threadIdx.x;
    for (int i = tid; i < HD * NV; i += blockDim.x) Rs[i] = R[i];
    if (tid < NV) rbs[tid] = rb[tid];
    __syncthreads();
    int n = blockIdx.x * blockDim.x + tid;
    if (n < N) {
        float a0 = rbs[0], a1 = rbs[1], a2 = rbs[2], a3 = rbs[3];
        const float* h = hV + (size_t)n * HD;
#pragma unroll 8
        for (int k = 0; k < HD; k++) {
            float hv = h[k];
            a0 += hv * Rs[k * NV + 0];
            a1 += hv * Rs[k * NV + 1];
            a2 += hv * Rs[k * NV + 2];
            a3 += hv * Rs[k * NV + 3];
        }
        out[(size_t)n * NV + 0] = a0;
        out[(size_t)n * NV + 1] = a1;
        out[(size_t)n * NV + 2] = a2;
        out[(size_t)n * NV + 3] = a3;
        out[(size_t)N * NV + n] = (float)S[n];
    }
}

// ---------------- launch ----------------------------------------------------
extern "C" void kernel_launch(void* const* d_in, const int* in_sizes, int n_in,
                              void* d_out, int out_size)
{
    const float* h_V  = (const float*)d_in[0];
    const float* h_E  = (const float*)d_in[1];
    const int*   Eidx = (const int*)d_in[2];
    const int*   bid  = (const int*)d_in[3];
    const int*   S    = (const int*)d_in[4];
    const float* W1   = (const float*)d_in[5];
    const float* b1   = (const float*)d_in[6];
    const float* W2   = (const float*)d_in[7];
    const float* b2   = (const float*)d_in[8];
    const float* W3   = (const float*)d_in[9];
    const float* b3   = (const float*)d_in[10];
    const float* ln1g = (const float*)d_in[11];
    const float* ln1b = (const float*)d_in[12];
    const float* Wi   = (const float*)d_in[13];
    const float* bi   = (const float*)d_in[14];
    const float* Wo   = (const float*)d_in[15];
    const float* bo   = (const float*)d_in[16];
    const float* ln2g = (const float*)d_in[17];
    const float* ln2b = (const float*)d_in[18];
    const float* P1   = (const float*)d_in[19];
    const float* P2   = (const float*)d_in[20];
    const float* p2b  = (const float*)d_in[21];
    const float* R    = (const float*)d_in[22];
    const float* rb   = (const float*)d_in[23];

    const int N = in_sizes[0] / HD;
    const int E = in_sizes[2] / 2;
    const int* esrc = Eidx;
    const int* edst = Eidx + E;

    float *p_hV, *p_agg, *p_tmp, *p_ffn, *p_xvs, *p_xvd, *p_deg, *p_pool, *p_pcnt;
    cudaGetSymbolAddress((void**)&p_hV,   g_hV);
    cudaGetSymbolAddress((void**)&p_agg,  g_agg);
    cudaGetSymbolAddress((void**)&p_tmp,  g_tmp);
    cudaGetSymbolAddress((void**)&p_ffn,  g_ffn);
    cudaGetSymbolAddress((void**)&p_xvs,  g_xvs);
    cudaGetSymbolAddress((void**)&p_xvd,  g_xvd);
    cudaGetSymbolAddress((void**)&p_deg,  g_deg);
    cudaGetSymbolAddress((void**)&p_pool, g_pool);
    cudaGetSymbolAddress((void**)&p_pcnt, g_pcnt);

    cudaFuncSetAttribute(edge_mlp_tc,
                         cudaFuncAttributeMaxDynamicSharedMemorySize, EDGE_SMEM);
    cudaFuncSetAttribute(gemm_tc,
                         cudaFuncAttributeMaxDynamicSharedMemorySize, GEMM_SMEM);

    copy_kernel<<<(N * HD + 255) / 256, 256>>>(p_hV, h_V, N * HD);

    zero_kernel<<<(N + 255) / 256, 256>>>(p_deg, N);
    deg_kernel<<<(E + 255) / 256, 256>>>(esrc, p_deg, E);

    const int edge_grid = (E + 127) / 128;
    const int mtiles = (N + 127) / 128;

    for (int l = 0; l < NL; ++l) {
        const float* W1l = W1 + (size_t)l * 3 * HD * HD;
        // fused pre-GEMMs: XVs = hV @ W1[128:256], XVd = hV @ W1[256:384]
        gemm_tc<<<dim3(1, mtiles, 2), 256, GEMM_SMEM>>>(
            p_hV, W1l + (size_t)HD * HD, W1l + (size_t)2 * HD * HD,
            nullptr, nullptr, p_xvs, p_xvd, N, HD, HD, 2);

        zero_kernel<<<(N * HD + 255) / 256, 256>>>(p_agg, N * HD);
        edge_mlp_tc<<<edge_grid, 256, EDGE_SMEM>>>(
            h_E, esrc, edst, p_xvs, p_xvd,
            W1l, b1 + (size_t)l * HD,
            W2 + (size_t)l * HD * HD, b2 + (size_t)l * HD,
            p_agg, E);
        // T = agg @ W3  (W3 hoisted out of the edge loop) — reuse p_xvs
        gemm_tc<<<dim3(1, mtiles, 1), 256, GEMM_SMEM>>>(
            p_agg, W3 + (size_t)l * HD * HD, nullptr,
            nullptr, nullptr, p_xvs, nullptr, N, HD, HD, 2);
        agg_ln_kernel<<<(N + 7) / 8, 256>>>(p_hV, p_xvs, p_deg, b3 + (size_t)l * HD,
                                            ln1g + (size_t)l * HD, ln1b + (size_t)l * HD, N);
        gemm_tc<<<dim3(4, mtiles, 1), 256, GEMM_SMEM>>>(
            p_hV, Wi + (size_t)l * HD * 4 * HD, nullptr,
            bi + (size_t)l * 4 * HD, nullptr, p_ffn, nullptr, N, 4 * HD, HD, 0);
        gemm_tc<<<dim3(1, mtiles, 1), 256, GEMM_SMEM>>>(
            p_ffn, Wo + (size_t)l * 4 * HD * HD, nullptr,
            bo + (size_t)l * HD, p_hV, p_tmp, nullptr, N, HD, 4 * HD, 1);
        ln_kernel<<<(N + 7) / 8, 256>>>(p_tmp, p_hV,
                                        ln2g + (size_t)l * HD, ln2b + (size_t)l * HD, N);
    }

    zero_kernel<<<(NB * HD + 255) / 256, 256>>>(p_pool, NB * HD);
    zero_kernel<<<1, 32>>>(p_pcnt, NB);
    pool_kernel<<<(N * HD + 255) / 256, 256>>>(p_hV, bid, p_pool, p_pcnt, N);

    float* out = (float*)d_out;
    head_kernel<<<1, 256>>>(p_pool, p_pcnt, P1, P2, p2b,
                            out + (size_t)N * NV + N);
    logits_kernel<<<(N + 255) / 256, 256>>>(p_hV, S, R, rb, out, N);
}

// round 9
// speedup vs baseline: 1.8179x; 1.3088x over previous
#include <cuda_runtime.h>
#include <cuda_fp16.h>
#include <math.h>

#define HD 128
#define NB 16     // batches
#define NV 4      // vocab
#define NL 6      // layers
#define MAXN 20000
#define MAXE 600000

// ---------------- scratch (static device allocs; cudaMalloc is banned) -----
__device__ float g_hV[MAXN * HD];
__device__ float g_agg[MAXN * HD];
__device__ float g_tmp[MAXN * HD];
__device__ float g_ffn[MAXN * 4 * HD];
__device__ float g_xvs[MAXN * HD];      // h_V @ W1_src ; later T = agg @ W3
__device__ float g_xvd[MAXN * HD];
__device__ float g_deg[MAXN];
__device__ float g_pool[NB * HD];
__device__ float g_pcnt[NB];

// ---------------- tiny utility kernels -------------------------------------
__global__ void zero_kernel(float* __restrict__ p, int n) {
    int i = blockIdx.x * blockDim.x + threadIdx.x;
    if (i < n) p[i] = 0.f;
}

__global__ void copy_kernel(float* __restrict__ dst, const float* __restrict__ src, int n) {
    int i = blockIdx.x * blockDim.x + threadIdx.x;
    if (i < n) dst[i] = src[i];
}

__global__ void deg_kernel(const int* __restrict__ src, float* __restrict__ deg, int E) {
    int i = blockIdx.x * blockDim.x + threadIdx.x;
    if (i < E) atomicAdd(&deg[src[i]], 1.f);
}

// ---------------- fp16 + fragment-major helpers -----------------------------
// m16n8k16 fragment-major smem layouts (one 32-bit word = half2 = k-pair):
//  A: group g = mtile*GS + ktile16 (132-word pitch). word = lane*4 + comp,
//     lane = (r%8)*4 + (pk%4), comp = ((r>>3)&1) + 2*(pk>=4), pk = k/2 (0..7)
//  B: group gb = ktile16*16 + ntile (66-word pitch). word = lane*2 + comp,
//     lane = (n%8)*4 + (pk%4), comp = (pk>=4)

__device__ __forceinline__ unsigned h2u(float lo, float hi) {
    __half2 h = __floats2half2_rn(lo, hi);
    return *(unsigned*)&h;
}

__device__ __forceinline__ void mma_f16(float c[4],
                                        unsigned a0, unsigned a1, unsigned a2, unsigned a3,
                                        unsigned b0, unsigned b1) {
    asm volatile(
        "mma.sync.aligned.m16n8k16.row.col.f32.f16.f16.f32 "
        "{%0,%1,%2,%3}, {%4,%5,%6,%7}, {%8,%9}, {%0,%1,%2,%3};"
        : "+f"(c[0]), "+f"(c[1]), "+f"(c[2]), "+f"(c[3])
        : "r"(a0), "r"(a1), "r"(a2), "r"(a3), "r"(b0), "r"(b1));
}

// ---- A chunk (128 rows x 32 k f32) -> 16 groups of half2 words, pitch 132
__device__ __forceinline__ void ldg_A(float4 v[4], const float* __restrict__ A,
                                      size_t lda, int row0, int M, int kglob0, int tid)
{
#pragma unroll
    for (int it = 0; it < 4; ++it) {
        int item = tid + it * 256;
        int row = item >> 3, q = item & 7;
        v[it] = make_float4(0.f, 0.f, 0.f, 0.f);
        if (row0 + row < M)
            v[it] = *(const float4*)(A + (size_t)(row0 + row) * lda + kglob0 + q * 4);
    }
}

__device__ __forceinline__ void sts_A_h(unsigned* __restrict__ As, const float4 v[4], int tid)
{
#pragma unroll
    for (int it = 0; it < 4; ++it) {
        int item = tid + it * 256;
        int row = item >> 3, q = item & 7;
        int g = ((row >> 4) << 1) + (q >> 2);
        int pk0 = (q & 3) * 2;
        int pk1 = pk0 + 1;
        int off0 = ((((row & 7) << 2) | (pk0 & 3)) << 2) + ((row >> 3) & 1) + (((pk0 >> 2) & 1) << 1);
        int off1 = ((((row & 7) << 2) | (pk1 & 3)) << 2) + ((row >> 3) & 1) + (((pk1 >> 2) & 1) << 1);
        As[g * 132 + off0] = h2u(v[it].x, v[it].y);
        As[g * 132 + off1] = h2u(v[it].z, v[it].w);
    }
}

// ---- B chunk (32 k x 128 n f32, row-major over n) -> 32 groups, pitch 66
__device__ __forceinline__ void ldg_Bh(float4 v0[2], float4 v1[2],
                                       const float* __restrict__ B, size_t ldb,
                                       int kglob0, int n0, int tid)
{
#pragma unroll
    for (int it = 0; it < 2; ++it) {
        int item = tid + it * 256;
        int p = item >> 5, q = item & 31;
        const float* base = B + (size_t)(kglob0 + 2 * p) * ldb + n0 + q * 4;
        v0[it] = *(const float4*)base;
        v1[it] = *(const float4*)(base + ldb);
    }
}

__device__ __forceinline__ void sts_Bh(unsigned* __restrict__ Bs,
                                       const float4 v0[2], const float4 v1[2], int tid)
{
#pragma unroll
    for (int it = 0; it < 2; ++it) {
        int item = tid + it * 256;
        int p = item >> 5, q = item & 31;
        int gb = (p >> 3) * 16 + (q >> 1);
        int pk = p & 7;
        int comp = (pk >> 2) & 1;
        const float* a = (const float*)&v0[it];
        const float* b = (const float*)&v1[it];
#pragma unroll
        for (int j = 0; j < 4; ++j) {
            int lane = ((((q & 1) << 2) + j) << 2) + (pk & 3);
            Bs[gb * 66 + lane * 2 + comp] = h2u(a[j], b[j]);
        }
    }
}

// one 32-k chunk (2 ktile16) of warp-tile 64x32 fp16 mma
__device__ __forceinline__ void mma_chunk_h(float acc[4][4][4],
                                            const unsigned* __restrict__ Af, int mg0, int gs, int gk0,
                                            const unsigned* __restrict__ Bs, int ng0, int lane)
{
#pragma unroll
    for (int kt = 0; kt < 2; ++kt) {
        uint4 a[4]; uint2 b[4];
#pragma unroll
        for (int mi = 0; mi < 4; ++mi)
            a[mi] = *(const uint4*)&Af[((mg0 + mi) * gs + gk0 + kt) * 132 + lane * 4];
#pragma unroll
        for (int ni = 0; ni < 4; ++ni)
            b[ni] = *(const uint2*)&Bs[((kt << 4) + ng0 + ni) * 66 + lane * 2];
#pragma unroll
        for (int mi = 0; mi < 4; ++mi)
#pragma unroll
            for (int ni = 0; ni < 4; ++ni)
                mma_f16(acc[mi][ni], a[mi].x, a[mi].y, a[mi].z, a[mi].w,
                        b[ni].x, b[ni].y);
    }
}

#define ACC_ZERO(acc) \
    _Pragma("unroll") for (int mi = 0; mi < 4; ++mi) \
    _Pragma("unroll") for (int ni = 0; ni < 4; ++ni) \
    _Pragma("unroll") for (int j = 0; j < 4; ++j) acc[mi][ni][j] = 0.f;

// ---------------- fused edge MLP (2 stages fp16; W3 hoisted) ----------------
// Stage 1: C1 = relu(hE @ W1a + XVs[src] + XVd[dst] + b1)    (K = 128)
// Stage 2: C2 = relu(C1 @ W2 + b2) ; red.v4 scatter C2 into agg[src]
#define WB_WORDS (4 * 32 * 66)     // 8448 = W1a resident; == Cs (64 groups * 132)
#define CHUNK_WORDS (16 * 132)     // 2112 (A chunk) == 32*66 (B chunk)
#define EDGE_SMEM ((WB_WORDS + 2 * CHUNK_WORDS + 256) * 4)
#define GEMM_SMEM ((4 * CHUNK_WORDS) * 4)

__global__ __launch_bounds__(256, 2)
void edge_mlp_tc(const float* __restrict__ hE,
                 const int* __restrict__ esrc,
                 const int* __restrict__ edst,
                 const float* __restrict__ XVs,
                 const float* __restrict__ XVd,
                 const float* __restrict__ W1a, const float* __restrict__ b1,
                 const float* __restrict__ W2,  const float* __restrict__ b2,
                 float* __restrict__ agg, int E)
{
    extern __shared__ unsigned smem_u[];
    unsigned* WB = smem_u;                  // W1a resident; later Cs
    unsigned* Asb[2] = { WB + WB_WORDS, WB + WB_WORDS + CHUNK_WORDS };
    int* s_src = (int*)(WB + WB_WORDS + 2 * CHUNK_WORDS);
    int* s_dst = s_src + 128;

    const int tid = threadIdx.x;
    const int lane = tid & 31;
    const int wid = tid >> 5;
    const int mrow0 = (wid >> 2) * 64;
    const int ncol0 = (wid & 3) * 32;
    const int mg0 = mrow0 >> 4;
    const int ng0 = ncol0 >> 3;
    const int lq = lane >> 2;
    const int lr = lane & 3;
    const int e0 = blockIdx.x * 128;

    if (tid < 128) {
        int e = e0 + tid;
        s_src[tid] = (e < E) ? esrc[e] : -1;
        s_dst[tid] = (e < E) ? edst[e] : -1;
    }

    float4 va[4];
    float4 v0[2], v1[2];
    float acc[4][4][4];

    // ================= stage 1: hE @ W1a (W resident, A ping-pong) ==========
    ACC_ZERO(acc);
#pragma unroll
    for (int c = 0; c < 4; ++c) {
        ldg_Bh(v0, v1, W1a, HD, c * 32, 0, tid);
        sts_Bh(WB + c * CHUNK_WORDS, v0, v1, tid);
    }
    ldg_A(va, hE, HD, e0, E, 0, tid);
    sts_A_h(Asb[0], va, tid);
    __syncthreads();

#pragma unroll
    for (int kc = 0; kc < 4; ++kc) {
        if (kc < 3) ldg_A(va, hE, HD, e0, E, (kc + 1) * 32, tid);
        mma_chunk_h(acc, Asb[kc & 1], mg0, 2, 0, WB + kc * CHUNK_WORDS, ng0, lane);
        if (kc < 3) sts_A_h(Asb[(kc + 1) & 1], va, tid);
        __syncthreads();
    }

    unsigned* Cs = WB;   // alias — all W1a reads are done

    // prefetch W2 chunk 0 (lands while epilogue runs)
    ldg_Bh(v0, v1, W2, HD, 0, 0, tid);

    // epilogue 1: + b1 + XVs[src] + XVd[dst], relu, half2 -> Cs (fp16 A-frag order)
#pragma unroll
    for (int ni = 0; ni < 4; ++ni) {
        int cb = ncol0 + ni * 8 + 2 * lr;
        int pk = cb >> 1;                 // global k-pair index 0..63
        int gk = pk >> 3;                 // ktile16
        int pkl = pk & 7;
        float b10 = b1[cb], b11 = b1[cb + 1];
#pragma unroll
        for (int mi = 0; mi < 4; ++mi) {
#pragma unroll
            for (int h = 0; h < 2; ++h) {
                int r = mrow0 + mi * 16 + lq + h * 8;
                int ns = s_src[r], nd = s_dst[r];
                float w0 = 0.f, w1 = 0.f;
                if (ns >= 0) {
                    float2 xs = *(const float2*)(XVs + (size_t)ns * HD + cb);
                    float2 xd = *(const float2*)(XVd + (size_t)nd * HD + cb);
                    w0 = acc[mi][ni][h * 2 + 0] + b10 + xs.x + xd.x;
                    w1 = acc[mi][ni][h * 2 + 1] + b11 + xs.y + xd.y;
                }
                int idx = ((mg0 + mi) * 8 + gk) * 132
                        + (((lq << 2) | (pkl & 3)) << 2) + h + (((pkl >> 2) & 1) << 1);
                Cs[idx] = h2u(fmaxf(w0, 0.f), fmaxf(w1, 0.f));
            }
        }
    }
    sts_Bh(Asb[0], v0, v1, tid);
    __syncthreads();

    // ================= stage 2: C1 @ W2 (W ping-pong) =======================
    ACC_ZERO(acc);
#pragma unroll
    for (int kc = 0; kc < 4; ++kc) {
        if (kc < 3) ldg_Bh(v0, v1, W2, HD, (kc + 1) * 32, 0, tid);
        mma_chunk_h(acc, Cs, mg0, 8, kc * 2, Asb[kc & 1], ng0, lane);
        if (kc < 3) sts_Bh(Asb[(kc + 1) & 1], v0, v1, tid);
        __syncthreads();
    }

    // epilogue 2 (final): relu(acc + b2) as half2 row-major (pitch 66) for scatter
#pragma unroll
    for (int ni = 0; ni < 4; ++ni) {
        int cb = ncol0 + ni * 8 + 2 * lr;
        int pk = cb >> 1;
        float b20 = b2[cb], b21 = b2[cb + 1];
#pragma unroll
        for (int mi = 0; mi < 4; ++mi) {
#pragma unroll
            for (int h = 0; h < 2; ++h) {
                int r = mrow0 + mi * 16 + lq + h * 8;
                Cs[r * 66 + pk] = h2u(fmaxf(acc[mi][ni][h * 2 + 0] + b20, 0.f),
                                      fmaxf(acc[mi][ni][h * 2 + 1] + b21, 0.f));
            }
        }
    }
    __syncthreads();

    // cooperative vector scatter of relu(C2): 128 rows x 32 float4
    for (int item = tid; item < 128 * 32; item += 256) {
        int row = item >> 5, q = item & 31;
        int node = s_src[row];
        if (node >= 0) {
            unsigned w0 = Cs[row * 66 + q * 2];
            unsigned w1 = Cs[row * 66 + q * 2 + 1];
            __half2 h0 = *(__half2*)&w0;
            __half2 h1 = *(__half2*)&w1;
            float* p = agg + (size_t)node * HD + q * 4;
            asm volatile("red.global.add.v4.f32 [%0], {%1,%2,%3,%4};"
                         :: "l"(p),
                            "f"(__low2float(h0)), "f"(__high2float(h0)),
                            "f"(__low2float(h1)), "f"(__high2float(h1))
                         : "memory");
        }
    }
}

// ---------------- fp16 node GEMM (128x128 tile, double-buffered) ------------
// epi 0: relu(A@B + bias); epi 1: A@B + bias + res; epi 2: A@B
// blockIdx.z selects (B,C) or (B2,C2) for the fused pre-GEMM pair
__global__ __launch_bounds__(256, 2)
void gemm_tc(const float* __restrict__ A, const float* __restrict__ B,
             const float* __restrict__ B2,
             const float* __restrict__ bias, const float* __restrict__ res,
             float* __restrict__ C, float* __restrict__ C2,
             int M, int N, int K, int epi)
{
    extern __shared__ unsigned smem_u[];
    unsigned* Asb[2] = { smem_u, smem_u + CHUNK_WORDS };
    unsigned* Bsb[2] = { smem_u + 2 * CHUNK_WORDS, smem_u + 3 * CHUNK_WORDS };

    const int tid = threadIdx.x;
    const int lane = tid & 31;
    const int wid = tid >> 5;
    const int mrow0 = (wid >> 2) * 64;
    const int ncol0 = (wid & 3) * 32;
    const int mg0 = mrow0 >> 4;
    const int ng0 = ncol0 >> 3;
    const int lq = lane >> 2;
    const int lr = lane & 3;
    const int m0 = blockIdx.y * 128, n0 = blockIdx.x * 128;
    if (blockIdx.z) { B = B2; C = C2; }

    float4 va[4];
    float4 v0[2], v1[2];
    float acc[4][4][4];
    ACC_ZERO(acc);

    const int nkc = K / 32;
    ldg_A(va, A, K, m0, M, 0, tid);
    ldg_Bh(v0, v1, B, N, 0, n0, tid);
    sts_A_h(Asb[0], va, tid);
    sts_Bh(Bsb[0], v0, v1, tid);
    __syncthreads();

    for (int kc = 0; kc < nkc; ++kc) {
        if (kc + 1 < nkc) {
            ldg_A(va, A, K, m0, M, (kc + 1) * 32, tid);
            ldg_Bh(v0, v1, B, N, (kc + 1) * 32, n0, tid);
        }
        mma_chunk_h(acc, Asb[kc & 1], mg0, 2, 0, Bsb[kc & 1], ng0, lane);
        if (kc + 1 < nkc) {
            sts_A_h(Asb[(kc + 1) & 1], va, tid);
            sts_Bh(Bsb[(kc + 1) & 1], v0, v1, tid);
        }
        __syncthreads();
    }

#pragma unroll
    for (int ni = 0; ni < 4; ++ni) {
        int c = n0 + ncol0 + ni * 8 + 2 * lr;
        float bb0 = (epi == 2) ? 0.f : bias[c];
        float bb1 = (epi == 2) ? 0.f : bias[c + 1];
#pragma unroll
        for (int mi = 0; mi < 4; ++mi) {
#pragma unroll
            for (int h = 0; h < 2; ++h) {
                int r = m0 + mrow0 + mi * 16 + lq + h * 8;
                if (r < M) {
                    float w0 = acc[mi][ni][h * 2 + 0] + bb0;
                    float w1 = acc[mi][ni][h * 2 + 1] + bb1;
                    if (epi == 0) { w0 = fmaxf(w0, 0.f); w1 = fmaxf(w1, 0.f); }
                    else if (epi == 1) {
                        w0 += res[(size_t)r * N + c];
                        w1 += res[(size_t)r * N + c + 1];
                    }
                    C[(size_t)r * N + c]     = w0;
                    C[(size_t)r * N + c + 1] = w1;
                }
            }
        }
    }
}

// ---------------- layernorm kernels (one warp per node, H=128) -------------
__device__ __forceinline__ float warp_sum(float v) {
#pragma unroll
    for (int o = 16; o > 0; o >>= 1) v += __shfl_xor_sync(0xffffffffu, v, o);
    return v;
}

// hV = LN(hV + T/deg + b3) in place   (T = agg @ W3)
__global__ void agg_ln_kernel(float* __restrict__ hV, const float* __restrict__ T,
                              const float* __restrict__ deg, const float* __restrict__ b3,
                              const float* __restrict__ g, const float* __restrict__ b,
                              int N)
{
    int warp = (blockIdx.x * blockDim.x + threadIdx.x) >> 5;
    int lane = threadIdx.x & 31;
    if (warp >= N) return;
    float d = fmaxf(deg[warp], 1.f);
    float x[4];
#pragma unroll
    for (int j = 0; j < 4; j++) {
        int c = j * 32 + lane;
        x[j] = hV[(size_t)warp * HD + c] + T[(size_t)warp * HD + c] / d + b3[c];
    }
    float s = warp_sum(x[0] + x[1] + x[2] + x[3]);
    float mu = s * (1.f / HD);
    float ss = warp_sum(x[0]*x[0] + x[1]*x[1] + x[2]*x[2] + x[3]*x[3]);
    float var = ss * (1.f / HD) - mu * mu;
    float inv = rsqrtf(var + 1e-5f);
#pragma unroll
    for (int j = 0; j < 4; j++) {
        int c = j * 32 + lane;
        hV[(size_t)warp * HD + c] = (x[j] - mu) * inv * g[c] + b[c];
    }
}

__global__ void ln_kernel(const float* __restrict__ x, float* __restrict__ out,
                          const float* __restrict__ g, const float* __restrict__ b,
                          int N)
{
    int warp = (blockIdx.x * blockDim.x + threadIdx.x) >> 5;
    int lane = threadIdx.x & 31;
    if (warp >= N) return;
    float v[4];
#pragma unroll
    for (int j = 0; j < 4; j++) v[j] = x[(size_t)warp * HD + j * 32 + lane];
    float s = warp_sum(v[0] + v[1] + v[2] + v[3]);
    float mu = s * (1.f / HD);
    float ss = warp_sum(v[0]*v[0] + v[1]*v[1] + v[2]*v[2] + v[3]*v[3]);
    float var = ss * (1.f / HD) - mu * mu;
    float inv = rsqrtf(var + 1e-5f);
#pragma unroll
    for (int j = 0; j < 4; j++) {
        int c = j * 32 + lane;
        out[(size_t)warp * HD + c] = (v[j] - mu) * inv * g[c] + b[c];
    }
}

// ---------------- pooling / heads ------------------------------------------
__global__ void pool_kernel(const float* __restrict__ hV, const int* __restrict__ batch_id,
                            float* __restrict__ pool, float* __restrict__ pcnt, int N)
{
    int i = blockIdx.x * blockDim.x + threadIdx.x;
    if (i < N * HD) {
        int n = i >> 7, c = i & 127;
        atomicAdd(&pool[batch_id[n] * HD + c], hV[i]);
    }
    if (i < N) atomicAdd(&pcnt[batch_id[i]], 1.f);
}

__global__ void head_kernel(const float* __restrict__ pool, const float* __restrict__ pcnt,
                            const float* __restrict__ P1, const float* __restrict__ P2,
                            const float* __restrict__ p2b, float* __restrict__ out)
{
    __shared__ float embs[NB * HD];
    __shared__ float t1[NB * HD];
    int tid = threadIdx.x;
    for (int i = tid; i < NB * HD; i += blockDim.x) {
        int bb = i >> 7;
        embs[i] = pool[i] / fmaxf(pcnt[bb], 1.f);
    }
    __syncthreads();
    for (int i = tid; i < NB * HD; i += blockDim.x) {
        int bb = i >> 7, j = i & 127;
        float s = 0.f;
        for (int k = 0; k < HD; k++) s += embs[bb * HD + k] * P1[k * HD + j];
        t1[i] = fmaxf(s, 0.f);
    }
    __syncthreads();
    for (int i = tid; i < NB * HD; i += blockDim.x) {
        int bb = i >> 7, j = i & 127;
        float s = p2b[j];
        for (int k = 0; k < HD; k++) s += t1[bb * HD + k] * P2[k * HD + j];
        out[i] = s;
    }
}

__global__ void logits_kernel(const float* __restrict__ hV, const int* __restrict__ S,
                              const float* __restrict__ R, const float* __restrict__ rb,
                              float* __restrict__ out, int N)
{
    __shared__ float Rs[HD * NV];
    __shared__ float rbs[NV];
    int tid = threadIdx.x;
    for (int i = tid; i < HD * NV; i += blockDim.x) Rs[i] = R[i];
    if (tid < NV) rbs[tid] = rb[tid];
    __syncthreads();
    int n = blockIdx.x * blockDim.x + tid;
    if (n < N) {
        float a0 = rbs[0], a1 = rbs[1], a2 = rbs[2], a3 = rbs[3];
        const float* h = hV + (size_t)n * HD;
#pragma unroll 8
        for (int k = 0; k < HD; k++) {
            float hv = h[k];
            a0 += hv * Rs[k * NV + 0];
            a1 += hv * Rs[k * NV + 1];
            a2 += hv * Rs[k * NV + 2];
            a3 += hv * Rs[k * NV + 3];
        }
        out[(size_t)n * NV + 0] = a0;
        out[(size_t)n * NV + 1] = a1;
        out[(size_t)n * NV + 2] = a2;
        out[(size_t)n * NV + 3] = a3;
        out[(size_t)N * NV + n] = (float)S[n];
    }
}

// ---------------- launch ----------------------------------------------------
extern "C" void kernel_launch(void* const* d_in, const int* in_sizes, int n_in,
                              void* d_out, int out_size)
{
    const float* h_V  = (const float*)d_in[0];
    const float* h_E  = (const float*)d_in[1];
    const int*   Eidx = (const int*)d_in[2];
    const int*   bid  = (const int*)d_in[3];
    const int*   S    = (const int*)d_in[4];
    const float* W1   = (const float*)d_in[5];
    const float* b1   = (const float*)d_in[6];
    const float* W2   = (const float*)d_in[7];
    const float* b2   = (const float*)d_in[8];
    const float* W3   = (const float*)d_in[9];
    const float* b3   = (const float*)d_in[10];
    const float* ln1g = (const float*)d_in[11];
    const float* ln1b = (const float*)d_in[12];
    const float* Wi   = (const float*)d_in[13];
    const float* bi   = (const float*)d_in[14];
    const float* Wo   = (const float*)d_in[15];
    const float* bo   = (const float*)d_in[16];
    const float* ln2g = (const float*)d_in[17];
    const float* ln2b = (const float*)d_in[18];
    const float* P1   = (const float*)d_in[19];
    const float* P2   = (const float*)d_in[20];
    const float* p2b  = (const float*)d_in[21];
    const float* R    = (const float*)d_in[22];
    const float* rb   = (const float*)d_in[23];

    const int N = in_sizes[0] / HD;
    const int E = in_sizes[2] / 2;
    const int* esrc = Eidx;
    const int* edst = Eidx + E;

    float *p_hV, *p_agg, *p_tmp, *p_ffn, *p_xvs, *p_xvd, *p_deg, *p_pool, *p_pcnt;
    cudaGetSymbolAddress((void**)&p_hV,   g_hV);
    cudaGetSymbolAddress((void**)&p_agg,  g_agg);
    cudaGetSymbolAddress((void**)&p_tmp,  g_tmp);
    cudaGetSymbolAddress((void**)&p_ffn,  g_ffn);
    cudaGetSymbolAddress((void**)&p_xvs,  g_xvs);
    cudaGetSymbolAddress((void**)&p_xvd,  g_xvd);
    cudaGetSymbolAddress((void**)&p_deg,  g_deg);
    cudaGetSymbolAddress((void**)&p_pool, g_pool);
    cudaGetSymbolAddress((void**)&p_pcnt, g_pcnt);

    cudaFuncSetAttribute(edge_mlp_tc,
                         cudaFuncAttributeMaxDynamicSharedMemorySize, EDGE_SMEM);
    cudaFuncSetAttribute(gemm_tc,
                         cudaFuncAttributeMaxDynamicSharedMemorySize, GEMM_SMEM);

    copy_kernel<<<(N * HD + 255) / 256, 256>>>(p_hV, h_V, N * HD);

    zero_kernel<<<(N + 255) / 256, 256>>>(p_deg, N);
    deg_kernel<<<(E + 255) / 256, 256>>>(esrc, p_deg, E);

    const int edge_grid = (E + 127) / 128;
    const int mtiles = (N + 127) / 128;

    for (int l = 0; l < NL; ++l) {
        const float* W1l = W1 + (size_t)l * 3 * HD * HD;
        // fused pre-GEMMs: XVs = hV @ W1[128:256], XVd = hV @ W1[256:384]
        gemm_tc<<<dim3(1, mtiles, 2), 256, GEMM_SMEM>>>(
            p_hV, W1l + (size_t)HD * HD, W1l + (size_t)2 * HD * HD,
            nullptr, nullptr, p_xvs, p_xvd, N, HD, HD, 2);

        zero_kernel<<<(N * HD + 255) / 256, 256>>>(p_agg, N * HD);
        edge_mlp_tc<<<edge_grid, 256, EDGE_SMEM>>>(
            h_E, esrc, edst, p_xvs, p_xvd,
            W1l, b1 + (size_t)l * HD,
            W2 + (size_t)l * HD * HD, b2 + (size_t)l * HD,
            p_agg, E);
        // T = agg @ W3  (hoisted) — reuse p_xvs
        gemm_tc<<<dim3(1, mtiles, 1), 256, GEMM_SMEM>>>(
            p_agg, W3 + (size_t)l * HD * HD, nullptr,
            nullptr, nullptr, p_xvs, nullptr, N, HD, HD, 2);
        agg_ln_kernel<<<(N + 7) / 8, 256>>>(p_hV, p_xvs, p_deg, b3 + (size_t)l * HD,
                                            ln1g + (size_t)l * HD, ln1b + (size_t)l * HD, N);
        gemm_tc<<<dim3(4, mtiles, 1), 256, GEMM_SMEM>>>(
            p_hV, Wi + (size_t)l * HD * 4 * HD, nullptr,
            bi + (size_t)l * 4 * HD, nullptr, p_ffn, nullptr, N, 4 * HD, HD, 0);
        gemm_tc<<<dim3(1, mtiles, 1), 256, GEMM_SMEM>>>(
            p_ffn, Wo + (size_t)l * 4 * HD * HD, nullptr,
            bo + (size_t)l * HD, p_hV, p_tmp, nullptr, N, HD, 4 * HD, 1);
        ln_kernel<<<(N + 7) / 8, 256>>>(p_tmp, p_hV,
                                        ln2g + (size_t)l * HD, ln2b + (size_t)l * HD, N);
    }

    zero_kernel<<<(NB * HD + 255) / 256, 256>>>(p_pool, NB * HD);
    zero_kernel<<<1, 32>>>(p_pcnt, NB);
    pool_kernel<<<(N * HD + 255) / 256, 256>>>(p_hV, bid, p_pool, p_pcnt, N);

    float* out = (float*)d_out;
    head_kernel<<<1, 256>>>(p_pool, p_pcnt, P1, P2, p2b,
                            out + (size_t)N * NV + N);
    logits_kernel<<<(N + 255) / 256, 256>>>(p_hV, S, R, rb, out, N);
}